// round 1
// baseline (speedup 1.0000x reference)
#include <cuda_runtime.h>
#include <math.h>

#define Cc  384
#define DIc 768
#define Sd  256
#define Rr  24
#define Kc  4
#define Bb  2
#define Ll  512
#define BL  (Bb*Ll)          // 1024
#define XD  (Rr + 2*Sd)      // 536

// ---------------- scratch (device globals; no allocation allowed) ----------------
__device__ float g_u[BL*Cc];
__device__ float g_xz[BL*2*DIc];
__device__ float g_xact[BL*DIc];
__device__ float g_xdbl[BL*XD];
__device__ float g_dt[BL*DIc];
__device__ float g_A[DIc*Sd];
__device__ int   g_powA;
__device__ float g_y[BL*DIc];
__device__ float g_res1[BL*Cc];
__device__ float g_t2[BL*Cc];

// ---------------- LayerNorm (row = 384, block = 128 threads) ----------------
__global__ __launch_bounds__(128) void ln_kernel(const float* __restrict__ x,
                                                 const float* __restrict__ gw,
                                                 const float* __restrict__ bw,
                                                 float* __restrict__ out) {
    int row = blockIdx.x;
    const float* xr = x + (size_t)row * Cc;
    float v[3];
#pragma unroll
    for (int i = 0; i < 3; i++) v[i] = xr[threadIdx.x + i*128];
    float s = v[0]+v[1]+v[2];
    float q = v[0]*v[0]+v[1]*v[1]+v[2]*v[2];
#pragma unroll
    for (int o = 16; o; o >>= 1) {
        s += __shfl_xor_sync(0xffffffffu, s, o);
        q += __shfl_xor_sync(0xffffffffu, q, o);
    }
    __shared__ float sh[8];
    int wid = threadIdx.x >> 5, ln = threadIdx.x & 31;
    if (ln == 0) { sh[wid] = s; sh[wid+4] = q; }
    __syncthreads();
    s = sh[0]+sh[1]+sh[2]+sh[3];
    q = sh[4]+sh[5]+sh[6]+sh[7];
    float mu  = s * (1.f/Cc);
    float var = q * (1.f/Cc) - mu*mu;
    float rs  = rsqrtf(var + 1e-5f);
#pragma unroll
    for (int i = 0; i < 3; i++) {
        int c = threadIdx.x + i*128;
        out[(size_t)row*Cc + c] = (v[i]-mu)*rs*gw[c] + bw[c];
    }
}

// ---------------- generic NT GEMM: out[M,N] = A[M,K] * W[N,K]^T (+bias)(+res) ----
template<bool BIAS, bool RES>
__global__ __launch_bounds__(256) void gemm_nt(const float* __restrict__ A,
                                               const float* __restrict__ W,
                                               const float* __restrict__ bias,
                                               const float* __restrict__ res,
                                               float* __restrict__ out,
                                               int M, int N, int Kd) {
    __shared__ float As[16][68];
    __shared__ float Ws[16][68];
    int tid = threadIdx.x;
    int tx = tid & 15, ty = tid >> 4;
    int m0 = blockIdx.y * 64, n0 = blockIdx.x * 64;
    float acc[4][4] = {};
    for (int k0 = 0; k0 < Kd; k0 += 16) {
#pragma unroll
        for (int i = tid; i < 64*16; i += 256) {
            int r = i >> 4, c = i & 15;
            int gk = k0 + c;
            As[c][r] = (m0 + r < M && gk < Kd) ? A[(size_t)(m0+r)*Kd + gk] : 0.f;
            Ws[c][r] = (n0 + r < N && gk < Kd) ? W[(size_t)(n0+r)*Kd + gk] : 0.f;
        }
        __syncthreads();
#pragma unroll
        for (int k = 0; k < 16; ++k) {
            float4 a4 = *(const float4*)&As[k][ty*4];
            float4 b4 = *(const float4*)&Ws[k][tx*4];
            float av[4] = {a4.x, a4.y, a4.z, a4.w};
            float bv[4] = {b4.x, b4.y, b4.z, b4.w};
#pragma unroll
            for (int i = 0; i < 4; i++)
#pragma unroll
                for (int j = 0; j < 4; j++) acc[i][j] += av[i]*bv[j];
        }
        __syncthreads();
    }
#pragma unroll
    for (int i = 0; i < 4; i++) {
        int gm = m0 + ty*4 + i;
        if (gm >= M) continue;
#pragma unroll
        for (int j = 0; j < 4; j++) {
            int gn = n0 + tx*4 + j;
            if (gn >= N) continue;
            float v = acc[i][j];
            if (BIAS) v += bias[gn];
            if (RES)  v += res[(size_t)gm*N + gn];
            out[(size_t)gm*N + gn] = v;
        }
    }
}

// ---------------- causal depthwise conv (K=4) + SiLU ----------------
__global__ void conv_kernel(const float* __restrict__ cw, const float* __restrict__ cb) {
    int i = blockIdx.x * blockDim.x + threadIdx.x;
    if (i >= BL*DIc) return;
    int d  = i % DIc;
    int bl = i / DIc;
    int l  = bl % Ll;
    int b  = bl / Ll;
    float acc = cb[d];
#pragma unroll
    for (int k = 0; k < Kc; ++k) {
        int ls = l - (Kc-1) + k;
        if (ls >= 0)
            acc += cw[d*Kc + k] * g_xz[(size_t)(b*Ll + ls)*(2*DIc) + d];
    }
    float sg = 1.f/(1.f + __expf(-acc));
    g_xact[i] = acc * sg;
}

// ---------------- dt projection (K=24) + softplus ----------------
__global__ __launch_bounds__(256) void dt_kernel(const float* __restrict__ Wdt,
                                                 const float* __restrict__ bdt) {
    __shared__ float sx[Rr];
    int row = blockIdx.x;
    if (threadIdx.x < Rr) sx[threadIdx.x] = g_xdbl[(size_t)row*XD + threadIdx.x];
    __syncthreads();
    for (int d = threadIdx.x; d < DIc; d += 256) {
        float acc = bdt[d];
#pragma unroll
        for (int r = 0; r < Rr; ++r) acc += sx[r] * Wdt[d*Rr + r];
        float sp = fmaxf(acc, 0.f) + log1pf(__expf(-fabsf(acc)));
        g_dt[(size_t)row*DIc + d] = sp;
    }
}

// ---------------- A precompute + structure check ----------------
__global__ void flag_kernel() { g_powA = 1; }

__global__ void a_kernel(const float* __restrict__ Alog) {
    int i = blockIdx.x*256 + threadIdx.x;
    if (i >= DIc*Sd) return;
    float a = -__expf(Alog[i]);
    g_A[i] = a;
    float tgt = (float)(i % Sd + 1);
    if (fabsf(a + tgt) > 1e-5f * tgt) g_powA = 0;
}

// ---------------- selective scan ----------------
struct Chunk { float dt0, dt1, du0, du1, xa0, xa1, z0, z1; };

__device__ __forceinline__ void load_chunk(int b, int tbase, int lane, int ch0, int ch1, Chunk& c) {
    size_t bl = (size_t)b*Ll + tbase + lane;
    c.dt0 = g_dt[bl*DIc + ch0];   c.dt1 = g_dt[bl*DIc + ch1];
    c.xa0 = g_xact[bl*DIc + ch0]; c.xa1 = g_xact[bl*DIc + ch1];
    c.du0 = c.dt0 * c.xa0;        c.du1 = c.dt1 * c.xa1;
    c.z0  = g_xz[bl*(2*DIc) + DIc + ch0];
    c.z1  = g_xz[bl*(2*DIc) + DIc + ch1];
}

__device__ __forceinline__ void load_row(const float* __restrict__ xd, int t, int s0,
                                         float4& B0, float4& B1, float4& C0, float4& C1) {
    const float* p = xd + (size_t)t*XD;
    B0 = *(const float4*)(p + Rr + s0);
    B1 = *(const float4*)(p + Rr + s0 + 4);
    C0 = *(const float4*)(p + Rr + Sd + s0);
    C1 = *(const float4*)(p + Rr + Sd + s0 + 4);
}

__device__ __forceinline__ void scan_step(int t, int lane, int s0, bool powA,
                                          const float (&a0)[8], const float (&a1)[8],
                                          float4 B0, float4 B1, float4 C0, float4 C1,
                                          float (&h0)[8], float (&h1)[8],
                                          const Chunk& ck, float D0, float D1,
                                          int ch0, int ch1, int b,
                                          const float* __restrict__ /*unused*/) {
    const unsigned m = 0xffffffffu;
    int ti = t & 31;
    float dt0 = __shfl_sync(m, ck.dt0, ti);
    float du0 = __shfl_sync(m, ck.du0, ti);
    float dt1 = __shfl_sync(m, ck.dt1, ti);
    float du1 = __shfl_sync(m, ck.du1, ti);
    float dA0[8], dA1[8];
    if (powA) {
        float E0 = __expf(-dt0), E1 = __expf(-dt1);
        dA0[0] = __expf(-dt0 * (float)(s0+1));
        dA1[0] = __expf(-dt1 * (float)(s0+1));
#pragma unroll
        for (int j = 1; j < 8; j++) { dA0[j] = dA0[j-1]*E0; dA1[j] = dA1[j-1]*E1; }
    } else {
#pragma unroll
        for (int j = 0; j < 8; j++) { dA0[j] = __expf(dt0*a0[j]); dA1[j] = __expf(dt1*a1[j]); }
    }
    float Bf[8] = {B0.x,B0.y,B0.z,B0.w,B1.x,B1.y,B1.z,B1.w};
    float Cf[8] = {C0.x,C0.y,C0.z,C0.w,C1.x,C1.y,C1.z,C1.w};
    float y0 = 0.f, y1 = 0.f;
#pragma unroll
    for (int j = 0; j < 8; j++) {
        h0[j] = dA0[j]*h0[j] + du0*Bf[j];
        y0   += h0[j]*Cf[j];
        h1[j] = dA1[j]*h1[j] + du1*Bf[j];
        y1   += h1[j]*Cf[j];
    }
#pragma unroll
    for (int o = 16; o; o >>= 1) {
        y0 += __shfl_xor_sync(m, y0, o);
        y1 += __shfl_xor_sync(m, y1, o);
    }
    if (lane == ti) {
        float sg0 = 1.f/(1.f + __expf(-ck.z0));
        float sg1 = 1.f/(1.f + __expf(-ck.z1));
        size_t bl = (size_t)b*Ll + t;
        g_y[bl*DIc + ch0] = (y0 + D0*ck.xa0) * (ck.z0 * sg0);
        g_y[bl*DIc + ch1] = (y1 + D1*ck.xa1) * (ck.z1 * sg1);
    }
}

// grid = Bb * (DIc/8) = 192 blocks, 128 threads (4 warps x 2 channels)
__global__ __launch_bounds__(128, 2) void scan_kernel(const float* __restrict__ Dvec) {
    const int w    = threadIdx.x >> 5;
    const int lane = threadIdx.x & 31;
    const int b    = blockIdx.x / (DIc/8);
    const int dg   = blockIdx.x % (DIc/8);
    const int ch0  = dg*8 + w*2, ch1 = ch0 + 1;
    const int s0   = lane*8;
    const float* xd = g_xdbl + (size_t)b*Ll*XD;

    float h0[8] = {}, h1[8] = {};
    float a0[8], a1[8];
    bool powA = (g_powA != 0);
    if (!powA) {
#pragma unroll
        for (int j = 0; j < 8; j++) {
            a0[j] = g_A[(size_t)ch0*Sd + s0 + j];
            a1[j] = g_A[(size_t)ch1*Sd + s0 + j];
        }
    } else {
#pragma unroll
        for (int j = 0; j < 8; j++) { a0[j] = 0.f; a1[j] = 0.f; }
    }
    float D0 = Dvec[ch0], D1 = Dvec[ch1];

    Chunk cur, nxt;
    load_chunk(b, 0, lane, ch0, ch1, cur);
    load_chunk(b, 32, lane, ch0, ch1, nxt);

    float4 aB0, aB1, aC0, aC1, bB0, bB1, bC0, bC1;
    load_row(xd, 0, s0, aB0, aB1, aC0, aC1);
    load_row(xd, 1, s0, bB0, bB1, bC0, bC1);

    for (int t = 0; t < Ll; t += 2) {
        if (t && (t & 31) == 0) {
            cur = nxt;
            if (t + 32 < Ll) load_chunk(b, t + 32, lane, ch0, ch1, nxt);
        }
        float4 nB0, nB1, nC0, nC1;
        bool pf0 = (t + 2 < Ll);
        if (pf0) load_row(xd, t + 2, s0, nB0, nB1, nC0, nC1);
        scan_step(t, lane, s0, powA, a0, a1, aB0, aB1, aC0, aC1,
                  h0, h1, cur, D0, D1, ch0, ch1, b, nullptr);
        if (pf0) { aB0 = nB0; aB1 = nB1; aC0 = nC0; aC1 = nC1; }

        float4 mB0, mB1, mC0, mC1;
        bool pf1 = (t + 3 < Ll);
        if (pf1) load_row(xd, t + 3, s0, mB0, mB1, mC0, mC1);
        scan_step(t + 1, lane, s0, powA, a0, a1, bB0, bB1, bC0, bC1,
                  h0, h1, cur, D0, D1, ch0, ch1, b, nullptr);
        if (pf1) { bB0 = mB0; bB1 = mB1; bC0 = mC0; bC1 = mC1; }
    }
}

// ---------------- launcher ----------------
extern "C" void kernel_launch(void* const* d_in, const int* in_sizes, int n_in,
                              void* d_out, int out_size) {
    const float* x          = (const float*)d_in[0];
    const float* ln1_g      = (const float*)d_in[1];
    const float* ln1_b      = (const float*)d_in[2];
    const float* ln2_g      = (const float*)d_in[3];
    const float* ln2_b      = (const float*)d_in[4];
    const float* head_w     = (const float*)d_in[5];
    const float* head_b     = (const float*)d_in[6];
    const float* in_proj_w  = (const float*)d_in[7];
    const float* conv_w     = (const float*)d_in[8];
    const float* conv_b     = (const float*)d_in[9];
    const float* x_proj_w   = (const float*)d_in[10];
    const float* dt_proj_w  = (const float*)d_in[11];
    const float* dt_proj_b  = (const float*)d_in[12];
    const float* A_log      = (const float*)d_in[13];
    const float* Dvec       = (const float*)d_in[14];
    const float* out_proj_w = (const float*)d_in[15];
    float* out = (float*)d_out;

    float *u, *xz, *xact, *xdbl, *dtb, *yb, *res1, *t2;
    cudaGetSymbolAddress((void**)&u,    g_u);
    cudaGetSymbolAddress((void**)&xz,   g_xz);
    cudaGetSymbolAddress((void**)&xact, g_xact);
    cudaGetSymbolAddress((void**)&xdbl, g_xdbl);
    cudaGetSymbolAddress((void**)&dtb,  g_dt);
    cudaGetSymbolAddress((void**)&yb,   g_y);
    cudaGetSymbolAddress((void**)&res1, g_res1);
    cudaGetSymbolAddress((void**)&t2,   g_t2);

    // independent precompute for the scan
    flag_kernel<<<1, 1>>>();
    a_kernel<<<(DIc*Sd + 255)/256, 256>>>(A_log);

    // u = ln1(x)
    ln_kernel<<<BL, 128>>>(x, ln1_g, ln1_b, u);

    // xz = u @ in_proj_w^T   (1024 x 1536, K=384)
    gemm_nt<false,false><<<dim3(2*DIc/64, BL/64), 256>>>(u, in_proj_w, nullptr, nullptr,
                                                         xz, BL, 2*DIc, Cc);

    // x_act = silu(conv(x_in) + conv_b)
    conv_kernel<<<(BL*DIc + 255)/256, 256>>>(conv_w, conv_b);

    // x_dbl = x_act @ x_proj_w^T   (1024 x 536, K=768)
    gemm_nt<false,false><<<dim3((XD + 63)/64, BL/64), 256>>>(xact, x_proj_w, nullptr, nullptr,
                                                             xdbl, BL, XD, DIc);

    // dt = softplus(dt_raw @ dt_proj_w^T + dt_proj_b)
    dt_kernel<<<BL, 256>>>(dt_proj_w, dt_proj_b);

    // selective scan + D-skip + z-gating -> g_y
    scan_kernel<<<Bb*(DIc/8), 128>>>(Dvec);

    // res1 = g_y @ out_proj_w^T + x   (1024 x 384, K=768)
    gemm_nt<false,true><<<dim3(Cc/64, BL/64), 256>>>(yb, out_proj_w, nullptr, x,
                                                     res1, BL, Cc, DIc);

    // t2 = ln2(res1)
    ln_kernel<<<BL, 128>>>(res1, ln2_g, ln2_b, t2);

    // out = t2 @ head_w^T + head_b + res1
    gemm_nt<true,true><<<dim3(Cc/64, BL/64), 256>>>(t2, head_w, head_b, res1,
                                                    out, BL, Cc, Cc);
}

// round 2
// speedup vs baseline: 1.1862x; 1.1862x over previous
#include <cuda_runtime.h>
#include <math.h>

#define Cc  384
#define DIc 768
#define Sd  256
#define Rr  24
#define Kc  4
#define Bb  2
#define Ll  512
#define BL  (Bb*Ll)          // 1024
#define XD  (Rr + 2*Sd)      // 536

typedef unsigned long long ull;

// ---------------- f32x2 packed helpers (sm_100+ FFMA2 path) ----------------
__device__ __forceinline__ ull fma2(ull a, ull b, ull c) {
    ull d;
    asm("fma.rn.f32x2 %0, %1, %2, %3;" : "=l"(d) : "l"(a), "l"(b), "l"(c));
    return d;
}
__device__ __forceinline__ ull mul2(ull a, ull b) {
    ull d;
    asm("mul.rn.f32x2 %0, %1, %2;" : "=l"(d) : "l"(a), "l"(b));
    return d;
}
__device__ __forceinline__ ull pack2(float x, float y) {
    ull d;
    asm("mov.b64 %0, {%1, %2};" : "=l"(d) : "f"(x), "f"(y));
    return d;
}
__device__ __forceinline__ float2 unpack2(ull v) {
    float2 r;
    asm("mov.b64 {%0, %1}, %2;" : "=f"(r.x), "=f"(r.y) : "l"(v));
    return r;
}

// ---------------- scratch (device globals; no allocation allowed) ----------------
__device__ __align__(16) float g_u[BL*Cc];
__device__ __align__(16) float g_xz[BL*2*DIc];
__device__ __align__(16) float g_xact[BL*DIc];
__device__ __align__(16) float g_xdbl[BL*XD];
__device__ __align__(16) float g_dt[BL*DIc];
__device__ __align__(16) float g_A[DIc*Sd];
__device__ int   g_powA;
__device__ __align__(16) float g_y[BL*DIc];
__device__ __align__(16) float g_res1[BL*Cc];
__device__ __align__(16) float g_t2[BL*Cc];

// ---------------- LayerNorm (row = 384, block = 128 threads) ----------------
__global__ __launch_bounds__(128) void ln_kernel(const float* __restrict__ x,
                                                 const float* __restrict__ gw,
                                                 const float* __restrict__ bw,
                                                 float* __restrict__ out) {
    int row = blockIdx.x;
    const float* xr = x + (size_t)row * Cc;
    float v[3];
#pragma unroll
    for (int i = 0; i < 3; i++) v[i] = xr[threadIdx.x + i*128];
    float s = v[0]+v[1]+v[2];
    float q = v[0]*v[0]+v[1]*v[1]+v[2]*v[2];
#pragma unroll
    for (int o = 16; o; o >>= 1) {
        s += __shfl_xor_sync(0xffffffffu, s, o);
        q += __shfl_xor_sync(0xffffffffu, q, o);
    }
    __shared__ float sh[8];
    int wid = threadIdx.x >> 5, ln = threadIdx.x & 31;
    if (ln == 0) { sh[wid] = s; sh[wid+4] = q; }
    __syncthreads();
    s = sh[0]+sh[1]+sh[2]+sh[3];
    q = sh[4]+sh[5]+sh[6]+sh[7];
    float mu  = s * (1.f/Cc);
    float var = q * (1.f/Cc) - mu*mu;
    float rs  = rsqrtf(var + 1e-5f);
#pragma unroll
    for (int i = 0; i < 3; i++) {
        int c = threadIdx.x + i*128;
        out[(size_t)row*Cc + c] = (v[i]-mu)*rs*gw[c] + bw[c];
    }
}

// ---------------- NT GEMM with f32x2 FFMA2 + double-buffered smem ----------------
// out[M,N] = A[M,K] * W[N,K]^T (+bias)(+res). tile 64x64, 256 thr, 4x4 microtile.
template<bool BIAS, bool RES>
__global__ __launch_bounds__(256) void gemm_nt(const float* __restrict__ A,
                                               const float* __restrict__ W,
                                               const float* __restrict__ bias,
                                               const float* __restrict__ res,
                                               float* __restrict__ out,
                                               int M, int N, int Kd) {
    __shared__ float As[2][16][68];
    __shared__ float Ws[2][16][68];
    int tid = threadIdx.x;
    int tx = tid & 15, ty = tid >> 4;
    int m0 = blockIdx.y * 64, n0 = blockIdx.x * 64;

    ull acc[4][2] = {};

    float ra[4], rw[4];
    // stage tile 0
    {
        int k0 = 0;
#pragma unroll
        for (int i = 0; i < 4; i++) {
            int idx = tid + i*256;
            int r = idx >> 4, c = idx & 15;
            int gk = k0 + c;
            ra[i] = (m0 + r < M && gk < Kd) ? A[(size_t)(m0+r)*Kd + gk] : 0.f;
            rw[i] = (n0 + r < N && gk < Kd) ? W[(size_t)(n0+r)*Kd + gk] : 0.f;
        }
#pragma unroll
        for (int i = 0; i < 4; i++) {
            int idx = tid + i*256;
            int r = idx >> 4, c = idx & 15;
            As[0][c][r] = ra[i];
            Ws[0][c][r] = rw[i];
        }
    }
    __syncthreads();

    int ntiles = (Kd + 15) >> 4;
    for (int tIdx = 0; tIdx < ntiles; tIdx++) {
        int buf = tIdx & 1;
        bool more = (tIdx + 1 < ntiles);
        if (more) {
            int k0 = (tIdx + 1) << 4;
#pragma unroll
            for (int i = 0; i < 4; i++) {
                int idx = tid + i*256;
                int r = idx >> 4, c = idx & 15;
                int gk = k0 + c;
                ra[i] = (m0 + r < M && gk < Kd) ? A[(size_t)(m0+r)*Kd + gk] : 0.f;
                rw[i] = (n0 + r < N && gk < Kd) ? W[(size_t)(n0+r)*Kd + gk] : 0.f;
            }
        }
#pragma unroll
        for (int k = 0; k < 16; ++k) {
            float4 a4 = *(const float4*)&As[buf][k][ty*4];
            ulonglong2 b2 = *(const ulonglong2*)&Ws[buf][k][tx*4];
            ull ap0 = pack2(a4.x, a4.x);
            ull ap1 = pack2(a4.y, a4.y);
            ull ap2 = pack2(a4.z, a4.z);
            ull ap3 = pack2(a4.w, a4.w);
            acc[0][0] = fma2(ap0, b2.x, acc[0][0]);
            acc[0][1] = fma2(ap0, b2.y, acc[0][1]);
            acc[1][0] = fma2(ap1, b2.x, acc[1][0]);
            acc[1][1] = fma2(ap1, b2.y, acc[1][1]);
            acc[2][0] = fma2(ap2, b2.x, acc[2][0]);
            acc[2][1] = fma2(ap2, b2.y, acc[2][1]);
            acc[3][0] = fma2(ap3, b2.x, acc[3][0]);
            acc[3][1] = fma2(ap3, b2.y, acc[3][1]);
        }
        if (more) {
            int nb = buf ^ 1;
#pragma unroll
            for (int i = 0; i < 4; i++) {
                int idx = tid + i*256;
                int r = idx >> 4, c = idx & 15;
                As[nb][c][r] = ra[i];
                Ws[nb][c][r] = rw[i];
            }
        }
        __syncthreads();
    }

#pragma unroll
    for (int i = 0; i < 4; i++) {
        int gm = m0 + ty*4 + i;
        if (gm >= M) continue;
#pragma unroll
        for (int j2 = 0; j2 < 2; j2++) {
            float2 v = unpack2(acc[i][j2]);
            int gn0 = n0 + tx*4 + j2*2;
            if (gn0 < N) {
                float o0 = v.x;
                if (BIAS) o0 += bias[gn0];
                if (RES)  o0 += res[(size_t)gm*N + gn0];
                out[(size_t)gm*N + gn0] = o0;
            }
            if (gn0 + 1 < N) {
                float o1 = v.y;
                if (BIAS) o1 += bias[gn0+1];
                if (RES)  o1 += res[(size_t)gm*N + gn0+1];
                out[(size_t)gm*N + gn0+1] = o1;
            }
        }
    }
}

// ---------------- causal depthwise conv (K=4) + SiLU ----------------
__global__ void conv_kernel(const float* __restrict__ cw, const float* __restrict__ cb) {
    int i = blockIdx.x * blockDim.x + threadIdx.x;
    if (i >= BL*DIc) return;
    int d  = i % DIc;
    int bl = i / DIc;
    int l  = bl % Ll;
    int b  = bl / Ll;
    float acc = cb[d];
#pragma unroll
    for (int k = 0; k < Kc; ++k) {
        int ls = l - (Kc-1) + k;
        if (ls >= 0)
            acc += cw[d*Kc + k] * g_xz[(size_t)(b*Ll + ls)*(2*DIc) + d];
    }
    float sg = 1.f/(1.f + __expf(-acc));
    g_xact[i] = acc * sg;
}

// ---------------- dt projection (K=24) + softplus ----------------
__global__ __launch_bounds__(256) void dt_kernel(const float* __restrict__ Wdt,
                                                 const float* __restrict__ bdt) {
    __shared__ float sx[Rr];
    int row = blockIdx.x;
    if (threadIdx.x < Rr) sx[threadIdx.x] = g_xdbl[(size_t)row*XD + threadIdx.x];
    __syncthreads();
    for (int d = threadIdx.x; d < DIc; d += 256) {
        float acc = bdt[d];
#pragma unroll
        for (int r = 0; r < Rr; ++r) acc += sx[r] * Wdt[d*Rr + r];
        float sp = fmaxf(acc, 0.f) + log1pf(__expf(-fabsf(acc)));
        g_dt[(size_t)row*DIc + d] = sp;
    }
}

// ---------------- A precompute + structure check ----------------
__global__ void flag_kernel() { g_powA = 1; }

__global__ void a_kernel(const float* __restrict__ Alog) {
    int i = blockIdx.x*256 + threadIdx.x;
    if (i >= DIc*Sd) return;
    float a = -__expf(Alog[i]);
    g_A[i] = a;
    float tgt = (float)(i % Sd + 1);
    if (fabsf(a + tgt) > 1e-5f * tgt) g_powA = 0;
}

// ---------------- selective scan v2 ----------------
struct Chunk { float dt0, dt1, du0, du1, xa0, xa1, z0, z1; };

__device__ __forceinline__ void load_chunk(int b, int tbase, int lane, int ch0, int ch1, Chunk& c) {
    size_t bl = (size_t)b*Ll + tbase + lane;
    c.dt0 = g_dt[bl*DIc + ch0];   c.dt1 = g_dt[bl*DIc + ch1];
    c.xa0 = g_xact[bl*DIc + ch0]; c.xa1 = g_xact[bl*DIc + ch1];
    c.du0 = c.dt0 * c.xa0;        c.du1 = c.dt1 * c.xa1;
    c.z0  = g_xz[bl*(2*DIc) + DIc + ch0];
    c.z1  = g_xz[bl*(2*DIc) + DIc + ch1];
}

struct RowU { ull B[4]; ull C[4]; };

__device__ __forceinline__ void load_row(const float* __restrict__ xd, int t, int s0, RowU& r) {
    const float* p = xd + (size_t)t*XD + Rr;
    ulonglong2 b01 = *(const ulonglong2*)(p + s0);
    ulonglong2 b23 = *(const ulonglong2*)(p + s0 + 4);
    ulonglong2 c01 = *(const ulonglong2*)(p + Sd + s0);
    ulonglong2 c23 = *(const ulonglong2*)(p + Sd + s0 + 4);
    r.B[0] = b01.x; r.B[1] = b01.y; r.B[2] = b23.x; r.B[3] = b23.y;
    r.C[0] = c01.x; r.C[1] = c01.y; r.C[2] = c23.x; r.C[3] = c23.y;
}

// one timestep for 2 channels; returns unreduced per-lane partials
__device__ __forceinline__ void step_update(int ti, const Chunk& ck, const RowU& r,
                                            ull (&H0)[4], ull (&H1)[4],
                                            bool powA, const float (&a0)[8], const float (&a1)[8],
                                            int s0, float& y0, float& y1) {
    const unsigned m = 0xffffffffu;
    float dt0 = __shfl_sync(m, ck.dt0, ti);
    float du0 = __shfl_sync(m, ck.du0, ti);
    float dt1 = __shfl_sync(m, ck.dt1, ti);
    float du1 = __shfl_sync(m, ck.du1, ti);
    ull P0[4], P1[4];
    if (powA) {
        float e0 = __expf(-dt0);
        float p0 = __expf(-dt0 * (float)(s0+1));
        ull E0 = pack2(e0*e0, e0*e0);
        P0[0] = pack2(p0, p0*e0);
        P0[1] = mul2(P0[0], E0);
        P0[2] = mul2(P0[1], E0);
        P0[3] = mul2(P0[2], E0);
        float e1 = __expf(-dt1);
        float p1 = __expf(-dt1 * (float)(s0+1));
        ull E1 = pack2(e1*e1, e1*e1);
        P1[0] = pack2(p1, p1*e1);
        P1[1] = mul2(P1[0], E1);
        P1[2] = mul2(P1[1], E1);
        P1[3] = mul2(P1[2], E1);
    } else {
#pragma unroll
        for (int j = 0; j < 4; j++) {
            P0[j] = pack2(__expf(dt0*a0[2*j]), __expf(dt0*a0[2*j+1]));
            P1[j] = pack2(__expf(dt1*a1[2*j]), __expf(dt1*a1[2*j+1]));
        }
    }
    ull du0p = pack2(du0, du0);
    ull du1p = pack2(du1, du1);
    ull ya0 = 0ull, ya1 = 0ull;
#pragma unroll
    for (int j = 0; j < 4; j++) {
        ull t0 = mul2(du0p, r.B[j]);
        H0[j] = fma2(P0[j], H0[j], t0);
        ya0   = fma2(H0[j], r.C[j], ya0);
        ull t1 = mul2(du1p, r.B[j]);
        H1[j] = fma2(P1[j], H1[j], t1);
        ya1   = fma2(H1[j], r.C[j], ya1);
    }
    float2 u0 = unpack2(ya0);
    float2 u1 = unpack2(ya1);
    y0 = u0.x + u0.y;
    y1 = u1.x + u1.y;
}

// grid = Bb * (DIc/16) = 96 blocks, 256 threads (8 warps x 2 channels = 16 ch/block)
__global__ __launch_bounds__(256, 1) void scan_kernel(const float* __restrict__ Dvec) {
    const int w    = threadIdx.x >> 5;
    const int lane = threadIdx.x & 31;
    const int b    = blockIdx.x / (DIc/16);
    const int dg   = blockIdx.x % (DIc/16);
    const int ch0  = dg*16 + w*2, ch1 = ch0 + 1;
    const int s0   = lane*8;
    const float* xd = g_xdbl + (size_t)b*Ll*XD;
    const unsigned m = 0xffffffffu;

    ull H0[4] = {}, H1[4] = {};
    float a0[8], a1[8];
    bool powA = (g_powA != 0);
    if (!powA) {
#pragma unroll
        for (int j = 0; j < 8; j++) {
            a0[j] = g_A[(size_t)ch0*Sd + s0 + j];
            a1[j] = g_A[(size_t)ch1*Sd + s0 + j];
        }
    } else {
#pragma unroll
        for (int j = 0; j < 8; j++) { a0[j] = 0.f; a1[j] = 0.f; }
    }
    float D0 = Dvec[ch0], D1 = Dvec[ch1];

    Chunk cur, nxt;
    load_chunk(b, 0, lane, ch0, ch1, cur);
    load_chunk(b, 32, lane, ch0, ch1, nxt);

    RowU rA, rB;
    load_row(xd, 0, s0, rA);
    load_row(xd, 1, s0, rB);

    for (int t = 0; t < Ll; t += 2) {
        if (t && (t & 31) == 0) {
            cur = nxt;
            if (t + 32 < Ll) load_chunk(b, t + 32, lane, ch0, ch1, nxt);
        }
        RowU rN0, rN1;
        bool pf0 = (t + 2 < Ll), pf1 = (t + 3 < Ll);
        if (pf0) load_row(xd, t + 2, s0, rN0);
        if (pf1) load_row(xd, t + 3, s0, rN1);

        int tiA = t & 31;
        float yA0, yA1, yB0, yB1;
        step_update(tiA,     cur, rA, H0, H1, powA, a0, a1, s0, yA0, yA1);
        step_update(tiA + 1, cur, rB, H0, H1, powA, a0, a1, s0, yB0, yB1);

        // four interleaved butterfly chains (latency-overlapped)
#pragma unroll
        for (int o = 16; o; o >>= 1) {
            yA0 += __shfl_xor_sync(m, yA0, o);
            yA1 += __shfl_xor_sync(m, yA1, o);
            yB0 += __shfl_xor_sync(m, yB0, o);
            yB1 += __shfl_xor_sync(m, yB1, o);
        }

        if (lane == tiA) {
            float sg0 = 1.f/(1.f + __expf(-cur.z0));
            float sg1 = 1.f/(1.f + __expf(-cur.z1));
            size_t bl = (size_t)b*Ll + t;
            g_y[bl*DIc + ch0] = (yA0 + D0*cur.xa0) * (cur.z0 * sg0);
            g_y[bl*DIc + ch1] = (yA1 + D1*cur.xa1) * (cur.z1 * sg1);
        }
        if (lane == tiA + 1) {
            float sg0 = 1.f/(1.f + __expf(-cur.z0));
            float sg1 = 1.f/(1.f + __expf(-cur.z1));
            size_t bl = (size_t)b*Ll + t + 1;
            g_y[bl*DIc + ch0] = (yB0 + D0*cur.xa0) * (cur.z0 * sg0);
            g_y[bl*DIc + ch1] = (yB1 + D1*cur.xa1) * (cur.z1 * sg1);
        }
        rA = rN0; rB = rN1;
    }
}

// ---------------- launcher ----------------
extern "C" void kernel_launch(void* const* d_in, const int* in_sizes, int n_in,
                              void* d_out, int out_size) {
    const float* x          = (const float*)d_in[0];
    const float* ln1_g      = (const float*)d_in[1];
    const float* ln1_b      = (const float*)d_in[2];
    const float* ln2_g      = (const float*)d_in[3];
    const float* ln2_b      = (const float*)d_in[4];
    const float* head_w     = (const float*)d_in[5];
    const float* head_b     = (const float*)d_in[6];
    const float* in_proj_w  = (const float*)d_in[7];
    const float* conv_w     = (const float*)d_in[8];
    const float* conv_b     = (const float*)d_in[9];
    const float* x_proj_w   = (const float*)d_in[10];
    const float* dt_proj_w  = (const float*)d_in[11];
    const float* dt_proj_b  = (const float*)d_in[12];
    const float* A_log      = (const float*)d_in[13];
    const float* Dvec       = (const float*)d_in[14];
    const float* out_proj_w = (const float*)d_in[15];
    float* out = (float*)d_out;

    float *u, *xz, *xact, *xdbl, *yb, *res1, *t2;
    cudaGetSymbolAddress((void**)&u,    g_u);
    cudaGetSymbolAddress((void**)&xz,   g_xz);
    cudaGetSymbolAddress((void**)&xact, g_xact);
    cudaGetSymbolAddress((void**)&xdbl, g_xdbl);
    cudaGetSymbolAddress((void**)&yb,   g_y);
    cudaGetSymbolAddress((void**)&res1, g_res1);
    cudaGetSymbolAddress((void**)&t2,   g_t2);

    // independent precompute for the scan
    flag_kernel<<<1, 1>>>();
    a_kernel<<<(DIc*Sd + 255)/256, 256>>>(A_log);

    // u = ln1(x)
    ln_kernel<<<BL, 128>>>(x, ln1_g, ln1_b, u);

    // xz = u @ in_proj_w^T   (1024 x 1536, K=384)
    gemm_nt<false,false><<<dim3(2*DIc/64, BL/64), 256>>>(u, in_proj_w, nullptr, nullptr,
                                                         xz, BL, 2*DIc, Cc);

    // x_act = silu(conv(x_in) + conv_b)
    conv_kernel<<<(BL*DIc + 255)/256, 256>>>(conv_w, conv_b);

    // x_dbl = x_act @ x_proj_w^T   (1024 x 536, K=768)
    gemm_nt<false,false><<<dim3((XD + 63)/64, BL/64), 256>>>(xact, x_proj_w, nullptr, nullptr,
                                                             xdbl, BL, XD, DIc);

    // dt = softplus(dt_raw @ dt_proj_w^T + dt_proj_b)
    dt_kernel<<<BL, 256>>>(dt_proj_w, dt_proj_b);

    // selective scan + D-skip + z-gating -> g_y
    scan_kernel<<<Bb*(DIc/16), 256>>>(Dvec);

    // res1 = g_y @ out_proj_w^T + x   (1024 x 384, K=768)
    gemm_nt<false,true><<<dim3(Cc/64, BL/64), 256>>>(yb, out_proj_w, nullptr, x,
                                                     res1, BL, Cc, DIc);

    // t2 = ln2(res1)
    ln_kernel<<<BL, 128>>>(res1, ln2_g, ln2_b, t2);

    // out = t2 @ head_w^T + head_b + res1
    gemm_nt<true,true><<<dim3(Cc/64, BL/64), 256>>>(t2, head_w, head_b, res1,
                                                    out, BL, Cc, Cc);
}

// round 3
// speedup vs baseline: 1.2038x; 1.0148x over previous
#include <cuda_runtime.h>
#include <math.h>

#define Cc  384
#define DIc 768
#define Sd  256
#define Rr  24
#define Kc  4
#define Bb  2
#define Ll  512
#define BL  (Bb*Ll)          // 1024
#define XD  (Rr + 2*Sd)      // 536

typedef unsigned long long ull;

// ---------------- f32x2 packed helpers (sm_100+ FFMA2 path) ----------------
__device__ __forceinline__ ull fma2(ull a, ull b, ull c) {
    ull d;
    asm("fma.rn.f32x2 %0, %1, %2, %3;" : "=l"(d) : "l"(a), "l"(b), "l"(c));
    return d;
}
__device__ __forceinline__ ull mul2(ull a, ull b) {
    ull d;
    asm("mul.rn.f32x2 %0, %1, %2;" : "=l"(d) : "l"(a), "l"(b));
    return d;
}
__device__ __forceinline__ ull pack2(float x, float y) {
    ull d;
    asm("mov.b64 %0, {%1, %2};" : "=l"(d) : "f"(x), "f"(y));
    return d;
}
__device__ __forceinline__ float2 unpack2(ull v) {
    float2 r;
    asm("mov.b64 {%0, %1}, %2;" : "=f"(r.x), "=f"(r.y) : "l"(v));
    return r;
}

// ---------------- scratch (device globals; no allocation allowed) ----------------
__device__ __align__(16) float g_u[BL*Cc];
__device__ __align__(16) float g_xz[BL*2*DIc];
__device__ __align__(16) float g_xact[BL*DIc];
__device__ __align__(16) float g_xdbl[BL*XD];
__device__ __align__(16) float g_dt[BL*DIc];
__device__ __align__(16) float g_e[BL*DIc];
__device__ __align__(16) float g_du[BL*DIc];
__device__ __align__(16) float g_A[DIc*Sd];
__device__ int   g_powA;
__device__ __align__(16) float g_y[BL*DIc];
__device__ __align__(16) float g_res1[BL*Cc];
__device__ __align__(16) float g_t2[BL*Cc];

// ---------------- LayerNorm (row = 384, block = 128 threads) ----------------
__global__ __launch_bounds__(128) void ln_kernel(const float* __restrict__ x,
                                                 const float* __restrict__ gw,
                                                 const float* __restrict__ bw,
                                                 float* __restrict__ out) {
    int row = blockIdx.x;
    const float* xr = x + (size_t)row * Cc;
    float v[3];
#pragma unroll
    for (int i = 0; i < 3; i++) v[i] = xr[threadIdx.x + i*128];
    float s = v[0]+v[1]+v[2];
    float q = v[0]*v[0]+v[1]*v[1]+v[2]*v[2];
#pragma unroll
    for (int o = 16; o; o >>= 1) {
        s += __shfl_xor_sync(0xffffffffu, s, o);
        q += __shfl_xor_sync(0xffffffffu, q, o);
    }
    __shared__ float sh[8];
    int wid = threadIdx.x >> 5, ln = threadIdx.x & 31;
    if (ln == 0) { sh[wid] = s; sh[wid+4] = q; }
    __syncthreads();
    s = sh[0]+sh[1]+sh[2]+sh[3];
    q = sh[4]+sh[5]+sh[6]+sh[7];
    float mu  = s * (1.f/Cc);
    float var = q * (1.f/Cc) - mu*mu;
    float rs  = rsqrtf(var + 1e-5f);
#pragma unroll
    for (int i = 0; i < 3; i++) {
        int c = threadIdx.x + i*128;
        out[(size_t)row*Cc + c] = (v[i]-mu)*rs*gw[c] + bw[c];
    }
}

// ---------------- NT GEMM: 64x64 tile, 64 threads, 8x8 microtile, FFMA2 ----------
// out[M,N] = A[M,K] * W[N,K]^T (+bias)(+res). M multiple of 64, K multiple of 8.
template<bool BIAS, bool RES>
__global__ __launch_bounds__(64, 8) void gemm_nt(const float* __restrict__ A,
                                                 const float* __restrict__ W,
                                                 const float* __restrict__ bias,
                                                 const float* __restrict__ res,
                                                 float* __restrict__ out,
                                                 int M, int N, int Kd) {
    __shared__ ull   As2[2][8][64];   // A pre-packed (a,a) pairs, k-major
    __shared__ float Ws [2][8][68];   // W floats, k-major, padded
    int tid = threadIdx.x;
    int tx = tid & 7, ty = tid >> 3;
    int m0 = blockIdx.y * 64, n0 = blockIdx.x * 64;

    ull acc[8][4] = {};

    const float* arow = A + (size_t)(m0 + tid) * Kd;
    bool wvalid = (n0 + tid) < N;
    const float* wrow = wvalid ? (W + (size_t)(n0 + tid) * Kd) : W;

    float ra[8], rw[8];
    // load tile 0
    {
        float4 a0 = *(const float4*)(arow + 0);
        float4 a1 = *(const float4*)(arow + 4);
        ra[0]=a0.x; ra[1]=a0.y; ra[2]=a0.z; ra[3]=a0.w;
        ra[4]=a1.x; ra[5]=a1.y; ra[6]=a1.z; ra[7]=a1.w;
        if (wvalid) {
            float4 w0 = *(const float4*)(wrow + 0);
            float4 w1 = *(const float4*)(wrow + 4);
            rw[0]=w0.x; rw[1]=w0.y; rw[2]=w0.z; rw[3]=w0.w;
            rw[4]=w1.x; rw[5]=w1.y; rw[6]=w1.z; rw[7]=w1.w;
        } else {
#pragma unroll
            for (int c = 0; c < 8; c++) rw[c] = 0.f;
        }
    }
#pragma unroll
    for (int c = 0; c < 8; c++) { As2[0][c][tid] = pack2(ra[c], ra[c]); Ws[0][c][tid] = rw[c]; }
    __syncthreads();

    int ntiles = Kd >> 3;
    for (int tI = 0; tI < ntiles; tI++) {
        int buf = tI & 1;
        bool more = (tI + 1 < ntiles);
        if (more) {
            int k0 = (tI + 1) << 3;
            float4 a0 = *(const float4*)(arow + k0);
            float4 a1 = *(const float4*)(arow + k0 + 4);
            ra[0]=a0.x; ra[1]=a0.y; ra[2]=a0.z; ra[3]=a0.w;
            ra[4]=a1.x; ra[5]=a1.y; ra[6]=a1.z; ra[7]=a1.w;
            if (wvalid) {
                float4 w0 = *(const float4*)(wrow + k0);
                float4 w1 = *(const float4*)(wrow + k0 + 4);
                rw[0]=w0.x; rw[1]=w0.y; rw[2]=w0.z; rw[3]=w0.w;
                rw[4]=w1.x; rw[5]=w1.y; rw[6]=w1.z; rw[7]=w1.w;
            }
        }
#pragma unroll
        for (int k = 0; k < 8; k++) {
            const ull* ap = &As2[buf][k][ty*8];
            ulonglong2 A01 = *(const ulonglong2*)(ap + 0);
            ulonglong2 A23 = *(const ulonglong2*)(ap + 2);
            ulonglong2 A45 = *(const ulonglong2*)(ap + 4);
            ulonglong2 A67 = *(const ulonglong2*)(ap + 6);
            ulonglong2 w01 = *(const ulonglong2*)&Ws[buf][k][tx*4];
            ulonglong2 w23 = *(const ulonglong2*)&Ws[buf][k][tx*4 + 32];
            ull a[8] = {A01.x, A01.y, A23.x, A23.y, A45.x, A45.y, A67.x, A67.y};
#pragma unroll
            for (int i = 0; i < 8; i++) {
                acc[i][0] = fma2(a[i], w01.x, acc[i][0]);
                acc[i][1] = fma2(a[i], w01.y, acc[i][1]);
                acc[i][2] = fma2(a[i], w23.x, acc[i][2]);
                acc[i][3] = fma2(a[i], w23.y, acc[i][3]);
            }
        }
        if (more) {
            int nb = buf ^ 1;
#pragma unroll
            for (int c = 0; c < 8; c++) { As2[nb][c][tid] = pack2(ra[c], ra[c]); Ws[nb][c][tid] = rw[c]; }
        }
        __syncthreads();
    }

#pragma unroll
    for (int i = 0; i < 8; i++) {
        int gm = m0 + ty*8 + i;
        float* orow = out + (size_t)gm * N;
        const float* rrow = RES ? (res + (size_t)gm * N) : (const float*)0;
#pragma unroll
        for (int j = 0; j < 4; j++) {
            int gn = n0 + ((j < 2) ? (tx*4 + j*2) : (32 + tx*4 + (j-2)*2));
            float2 v = unpack2(acc[i][j]);
            if (gn < N) {
                float o = v.x;
                if (BIAS) o += bias[gn];
                if (RES)  o += rrow[gn];
                orow[gn] = o;
            }
            if (gn + 1 < N) {
                float o = v.y;
                if (BIAS) o += bias[gn+1];
                if (RES)  o += rrow[gn+1];
                orow[gn+1] = o;
            }
        }
    }
}

// ---------------- causal depthwise conv (K=4) + SiLU ----------------
__global__ void conv_kernel(const float* __restrict__ cw, const float* __restrict__ cb) {
    int i = blockIdx.x * blockDim.x + threadIdx.x;
    if (i >= BL*DIc) return;
    int d  = i % DIc;
    int bl = i / DIc;
    int l  = bl % Ll;
    int b  = bl / Ll;
    float acc = cb[d];
#pragma unroll
    for (int k = 0; k < Kc; ++k) {
        int ls = l - (Kc-1) + k;
        if (ls >= 0)
            acc += cw[d*Kc + k] * g_xz[(size_t)(b*Ll + ls)*(2*DIc) + d];
    }
    float sg = 1.f/(1.f + __expf(-acc));
    g_xact[i] = acc * sg;
}

// ---------------- dt projection (K=24) + softplus + exp/du precompute ----------
__global__ __launch_bounds__(256) void dt_kernel(const float* __restrict__ Wdt,
                                                 const float* __restrict__ bdt) {
    __shared__ float sx[Rr];
    int row = blockIdx.x;
    if (threadIdx.x < Rr) sx[threadIdx.x] = g_xdbl[(size_t)row*XD + threadIdx.x];
    __syncthreads();
    for (int d = threadIdx.x; d < DIc; d += 256) {
        float acc = bdt[d];
#pragma unroll
        for (int r = 0; r < Rr; ++r) acc += sx[r] * Wdt[d*Rr + r];
        float sp = fmaxf(acc, 0.f) + log1pf(__expf(-fabsf(acc)));
        size_t idx = (size_t)row*DIc + d;
        g_dt[idx] = sp;
        g_e[idx]  = __expf(-sp);
        g_du[idx] = sp * g_xact[idx];
    }
}

// ---------------- A precompute + structure check ----------------
__global__ void flag_kernel() { g_powA = 1; }

__global__ void a_kernel(const float* __restrict__ Alog) {
    int i = blockIdx.x*256 + threadIdx.x;
    if (i >= DIc*Sd) return;
    float a = -__expf(Alog[i]);
    g_A[i] = a;
    float tgt = (float)(i % Sd + 1);
    if (fabsf(a + tgt) > 1e-5f * tgt) g_powA = 0;
}

// ---------------- selective scan v3 ----------------
struct Chunk { float dt0, dt1, e0, e1, du0, du1, xa0, xa1, z0, z1; };

__device__ __forceinline__ void load_chunk(int b, int tbase, int lane, int ch0, int ch1, Chunk& c) {
    size_t bl = (size_t)b*Ll + tbase + lane;
    size_t i0 = bl*DIc + ch0, i1 = bl*DIc + ch1;
    c.dt0 = g_dt[i0];  c.dt1 = g_dt[i1];
    c.e0  = g_e[i0];   c.e1  = g_e[i1];
    c.du0 = g_du[i0];  c.du1 = g_du[i1];
    c.xa0 = g_xact[i0]; c.xa1 = g_xact[i1];
    c.z0  = g_xz[bl*(2*DIc) + DIc + ch0];
    c.z1  = g_xz[bl*(2*DIc) + DIc + ch1];
}

struct RowU { ull B[4]; ull C[4]; };

__device__ __forceinline__ void load_row(const float* __restrict__ xd, int t, int s0, RowU& r) {
    const float* p = xd + (size_t)t*XD + Rr;
    ulonglong2 b01 = *(const ulonglong2*)(p + s0);
    ulonglong2 b23 = *(const ulonglong2*)(p + s0 + 4);
    ulonglong2 c01 = *(const ulonglong2*)(p + Sd + s0);
    ulonglong2 c23 = *(const ulonglong2*)(p + Sd + s0 + 4);
    r.B[0] = b01.x; r.B[1] = b01.y; r.B[2] = b23.x; r.B[3] = b23.y;
    r.C[0] = c01.x; r.C[1] = c01.y; r.C[2] = c23.x; r.C[3] = c23.y;
}

// one timestep for 2 channels; stores per-lane partials to smem slot
__device__ __forceinline__ void step_update(int ti, int slot, const Chunk& ck, const RowU& r,
                                            ull (&H0)[4], ull (&H1)[4],
                                            bool powA, const float (&a0)[8], const float (&a1)[8],
                                            float nS1, float* yb0, float* yb1, int lane) {
    const unsigned m = 0xffffffffu;
    float dt0 = __shfl_sync(m, ck.dt0, ti);
    float dt1 = __shfl_sync(m, ck.dt1, ti);
    float e0  = __shfl_sync(m, ck.e0,  ti);
    float e1  = __shfl_sync(m, ck.e1,  ti);
    float du0 = __shfl_sync(m, ck.du0, ti);
    float du1 = __shfl_sync(m, ck.du1, ti);
    ull P0[4], P1[4];
    if (powA) {
        float p0 = __expf(dt0 * nS1);   // exp(-dt*(s0+1))
        float p1 = __expf(dt1 * nS1);
        ull E0 = pack2(e0*e0, e0*e0);
        ull E1 = pack2(e1*e1, e1*e1);
        P0[0] = pack2(p0, p0*e0);
        P1[0] = pack2(p1, p1*e1);
        P0[1] = mul2(P0[0], E0); P0[2] = mul2(P0[1], E0); P0[3] = mul2(P0[2], E0);
        P1[1] = mul2(P1[0], E1); P1[2] = mul2(P1[1], E1); P1[3] = mul2(P1[2], E1);
    } else {
#pragma unroll
        for (int j = 0; j < 4; j++) {
            P0[j] = pack2(__expf(dt0*a0[2*j]), __expf(dt0*a0[2*j+1]));
            P1[j] = pack2(__expf(dt1*a1[2*j]), __expf(dt1*a1[2*j+1]));
        }
    }
    ull du0p = pack2(du0, du0);
    ull du1p = pack2(du1, du1);
    ull ya0 = 0ull, ya1 = 0ull;
#pragma unroll
    for (int j = 0; j < 4; j++) {
        H0[j] = fma2(P0[j], H0[j], mul2(du0p, r.B[j]));
        ya0   = fma2(H0[j], r.C[j], ya0);
        H1[j] = fma2(P1[j], H1[j], mul2(du1p, r.B[j]));
        ya1   = fma2(H1[j], r.C[j], ya1);
    }
    float2 u0 = unpack2(ya0);
    float2 u1 = unpack2(ya1);
    yb0[lane*17 + slot] = u0.x + u0.y;
    yb1[lane*17 + slot] = u1.x + u1.y;
}

// grid = Bb * (DIc/12) = 128 blocks, 192 threads (6 warps x 2 channels)
__global__ __launch_bounds__(192, 1) void scan_kernel(const float* __restrict__ Dvec) {
    __shared__ float ybuf[6][2][32*17];   // [warp][ch][lane*17 + slot]
    const int w    = threadIdx.x >> 5;
    const int lane = threadIdx.x & 31;
    const int b    = blockIdx.x / (DIc/12);
    const int dg   = blockIdx.x % (DIc/12);
    const int ch0  = dg*12 + w*2, ch1 = ch0 + 1;
    const int s0   = lane*8;
    const float nS1 = -(float)(s0 + 1);
    const float* xd = g_xdbl + (size_t)b*Ll*XD;
    float* yb0 = ybuf[w][0];
    float* yb1 = ybuf[w][1];

    ull H0[4] = {}, H1[4] = {};
    float a0[8], a1[8];
    bool powA = (g_powA != 0);
    if (!powA) {
#pragma unroll
        for (int j = 0; j < 8; j++) {
            a0[j] = g_A[(size_t)ch0*Sd + s0 + j];
            a1[j] = g_A[(size_t)ch1*Sd + s0 + j];
        }
    } else {
#pragma unroll
        for (int j = 0; j < 8; j++) { a0[j] = 0.f; a1[j] = 0.f; }
    }
    float D0 = Dvec[ch0], D1 = Dvec[ch1];

    Chunk cur, nxt;
    load_chunk(b, 0, lane, ch0, ch1, cur);
    load_chunk(b, 32, lane, ch0, ch1, nxt);

    RowU r0, r1;
    load_row(xd, 0, s0, r0);
    load_row(xd, 1, s0, r1);

    for (int c = 0; c < Ll/32; c++) {
        int tb = c*32;
#pragma unroll
        for (int half = 0; half < 2; half++) {
#pragma unroll 2
            for (int i = 0; i < 16; i += 2) {
                int t = tb + half*16 + i;
                RowU rn0, rn1;
                bool p0 = (t + 2 < Ll), p1 = (t + 3 < Ll);
                if (p0) load_row(xd, t + 2, s0, rn0);
                if (p1) load_row(xd, t + 3, s0, rn1);
                int ti = half*16 + i;
                step_update(ti,     i,     cur, r0, H0, H1, powA, a0, a1, nS1, yb0, yb1, lane);
                step_update(ti + 1, i + 1, cur, r1, H0, H1, powA, a0, a1, nS1, yb0, yb1, lane);
                r0 = rn0; r1 = rn1;
            }
            __syncwarp();
            // reduce: 32 t's per chunk, 16 per half; lane pairs (l, l+16) share t
            {
                int t15 = lane & 15;
                int lb  = (lane < 16) ? 0 : 16;
                float acc0 = 0.f, acc1 = 0.f;
#pragma unroll
                for (int l = 0; l < 16; l++) {
                    acc0 += yb0[(lb + l)*17 + t15];
                    acc1 += yb1[(lb + l)*17 + t15];
                }
                acc0 += __shfl_xor_sync(0xffffffffu, acc0, 16);
                acc1 += __shfl_xor_sync(0xffffffffu, acc1, 16);
                bool mine = half ? (lane >= 16) : (lane < 16);
                if (mine) {
                    float sg0 = 1.f/(1.f + __expf(-cur.z0));
                    float sg1 = 1.f/(1.f + __expf(-cur.z1));
                    size_t bl = (size_t)b*Ll + tb + lane;
                    g_y[bl*DIc + ch0] = (acc0 + D0*cur.xa0) * (cur.z0 * sg0);
                    g_y[bl*DIc + ch1] = (acc1 + D1*cur.xa1) * (cur.z1 * sg1);
                }
            }
            __syncwarp();
        }
        cur = nxt;
        if (tb + 64 < Ll) load_chunk(b, tb + 64, lane, ch0, ch1, nxt);
    }
}

// ---------------- launcher ----------------
extern "C" void kernel_launch(void* const* d_in, const int* in_sizes, int n_in,
                              void* d_out, int out_size) {
    const float* x          = (const float*)d_in[0];
    const float* ln1_g      = (const float*)d_in[1];
    const float* ln1_b      = (const float*)d_in[2];
    const float* ln2_g      = (const float*)d_in[3];
    const float* ln2_b      = (const float*)d_in[4];
    const float* head_w     = (const float*)d_in[5];
    const float* head_b     = (const float*)d_in[6];
    const float* in_proj_w  = (const float*)d_in[7];
    const float* conv_w     = (const float*)d_in[8];
    const float* conv_b     = (const float*)d_in[9];
    const float* x_proj_w   = (const float*)d_in[10];
    const float* dt_proj_w  = (const float*)d_in[11];
    const float* dt_proj_b  = (const float*)d_in[12];
    const float* A_log      = (const float*)d_in[13];
    const float* Dvec       = (const float*)d_in[14];
    const float* out_proj_w = (const float*)d_in[15];
    float* out = (float*)d_out;

    float *u, *xz, *xact, *xdbl, *yb, *res1, *t2;
    cudaGetSymbolAddress((void**)&u,    g_u);
    cudaGetSymbolAddress((void**)&xz,   g_xz);
    cudaGetSymbolAddress((void**)&xact, g_xact);
    cudaGetSymbolAddress((void**)&xdbl, g_xdbl);
    cudaGetSymbolAddress((void**)&yb,   g_y);
    cudaGetSymbolAddress((void**)&res1, g_res1);
    cudaGetSymbolAddress((void**)&t2,   g_t2);

    // independent precompute for the scan
    flag_kernel<<<1, 1>>>();
    a_kernel<<<(DIc*Sd + 255)/256, 256>>>(A_log);

    // u = ln1(x)
    ln_kernel<<<BL, 128>>>(x, ln1_g, ln1_b, u);

    // xz = u @ in_proj_w^T   (1024 x 1536, K=384)
    gemm_nt<false,false><<<dim3(2*DIc/64, BL/64), 64>>>(u, in_proj_w, nullptr, nullptr,
                                                        xz, BL, 2*DIc, Cc);

    // x_act = silu(conv(x_in) + conv_b)
    conv_kernel<<<(BL*DIc + 255)/256, 256>>>(conv_w, conv_b);

    // x_dbl = x_act @ x_proj_w^T   (1024 x 536, K=768)
    gemm_nt<false,false><<<dim3((XD + 63)/64, BL/64), 64>>>(xact, x_proj_w, nullptr, nullptr,
                                                            xdbl, BL, XD, DIc);

    // dt = softplus(dt_raw @ dt_proj_w^T + dt_proj_b), plus exp(-dt), dt*xact
    dt_kernel<<<BL, 256>>>(dt_proj_w, dt_proj_b);

    // selective scan + D-skip + z-gating -> g_y
    scan_kernel<<<Bb*(DIc/12), 192>>>(Dvec);

    // res1 = g_y @ out_proj_w^T + x   (1024 x 384, K=768)
    gemm_nt<false,true><<<dim3(Cc/64, BL/64), 64>>>(yb, out_proj_w, nullptr, x,
                                                    res1, BL, Cc, DIc);

    // t2 = ln2(res1)
    ln_kernel<<<BL, 128>>>(res1, ln2_g, ln2_b, t2);

    // out = t2 @ head_w^T + head_b + res1
    gemm_nt<true,true><<<dim3(Cc/64, BL/64), 64>>>(t2, head_w, head_b, res1,
                                                   out, BL, Cc, Cc);
}

// round 4
// speedup vs baseline: 1.3703x; 1.1383x over previous
#include <cuda_runtime.h>
#include <math.h>

#define Cc  384
#define DIc 768
#define Sd  256
#define Rr  24
#define Kc  4
#define Bb  2
#define Ll  512
#define BL  (Bb*Ll)          // 1024
#define XD  (Rr + 2*Sd)      // 536

typedef unsigned long long ull;

// ---------------- f32x2 packed helpers (sm_100+ FFMA2 path) ----------------
__device__ __forceinline__ ull fma2(ull a, ull b, ull c) {
    ull d;
    asm("fma.rn.f32x2 %0, %1, %2, %3;" : "=l"(d) : "l"(a), "l"(b), "l"(c));
    return d;
}
__device__ __forceinline__ ull mul2(ull a, ull b) {
    ull d;
    asm("mul.rn.f32x2 %0, %1, %2;" : "=l"(d) : "l"(a), "l"(b));
    return d;
}
__device__ __forceinline__ ull pack2(float x, float y) {
    ull d;
    asm("mov.b64 %0, {%1, %2};" : "=l"(d) : "f"(x), "f"(y));
    return d;
}
__device__ __forceinline__ float2 unpack2(ull v) {
    float2 r;
    asm("mov.b64 {%0, %1}, %2;" : "=f"(r.x), "=f"(r.y) : "l"(v));
    return r;
}

// ---------------- scratch (device globals; no allocation allowed) ----------------
__device__ __align__(16) float g_u[BL*Cc];
__device__ __align__(16) float g_xz[BL*2*DIc];
__device__ __align__(16) float g_xact[BL*DIc];
__device__ __align__(16) float g_xdbl[BL*XD];
__device__ __align__(16) float g_dt[BL*DIc];
__device__ __align__(16) float g_e[BL*DIc];
__device__ __align__(16) float g_du[BL*DIc];
__device__ __align__(16) float g_A[DIc*Sd];
__device__ int   g_powA;
__device__ __align__(16) float g_y[BL*DIc];
__device__ __align__(16) float g_res1[BL*Cc];
__device__ __align__(16) float g_t2[BL*Cc];

// ---------------- LayerNorm (row = 384, block = 128 threads) ----------------
__global__ __launch_bounds__(128) void ln_kernel(const float* __restrict__ x,
                                                 const float* __restrict__ gw,
                                                 const float* __restrict__ bw,
                                                 float* __restrict__ out) {
    int row = blockIdx.x;
    const float* xr = x + (size_t)row * Cc;
    float v[3];
#pragma unroll
    for (int i = 0; i < 3; i++) v[i] = xr[threadIdx.x + i*128];
    float s = v[0]+v[1]+v[2];
    float q = v[0]*v[0]+v[1]*v[1]+v[2]*v[2];
#pragma unroll
    for (int o = 16; o; o >>= 1) {
        s += __shfl_xor_sync(0xffffffffu, s, o);
        q += __shfl_xor_sync(0xffffffffu, q, o);
    }
    __shared__ float sh[8];
    int wid = threadIdx.x >> 5, ln = threadIdx.x & 31;
    if (ln == 0) { sh[wid] = s; sh[wid+4] = q; }
    __syncthreads();
    s = sh[0]+sh[1]+sh[2]+sh[3];
    q = sh[4]+sh[5]+sh[6]+sh[7];
    float mu  = s * (1.f/Cc);
    float var = q * (1.f/Cc) - mu*mu;
    float rs  = rsqrtf(var + 1e-5f);
#pragma unroll
    for (int i = 0; i < 3; i++) {
        int c = threadIdx.x + i*128;
        out[(size_t)row*Cc + c] = (v[i]-mu)*rs*gw[c] + bw[c];
    }
}

// ---------------- NT GEMM: 64x64 tile, 128 threads, 4m x 8n microtile, FFMA2 ----
// out[M,N] = A[M,K] * W[N,K]^T (+bias)(+res). M mult of 64, K mult of 8.
template<bool BIAS, bool RES>
__global__ __launch_bounds__(128, 5) void gemm_nt(const float* __restrict__ A,
                                                  const float* __restrict__ W,
                                                  const float* __restrict__ bias,
                                                  const float* __restrict__ res,
                                                  float* __restrict__ out,
                                                  int M, int N, int Kd) {
    __shared__ ull   As2[2][8][64];   // A packed (a,a), k-major
    __shared__ float Ws [2][8][72];   // W floats, k-major, 16B-aligned pitch
    int tid = threadIdx.x;
    int tx = tid & 7, ty = tid >> 3;
    int m0 = blockIdx.y * 64, n0 = blockIdx.x * 64;

    ull acc[4][4] = {};

    int lr = tid >> 1;            // row 0..63
    int kh = (tid & 1) * 4;       // k-half offset 0 or 4
    const float* arow = A + (size_t)(m0 + lr) * Kd + kh;
    bool wv = (n0 + lr) < N;
    const float* wrow = wv ? (W + (size_t)(n0 + lr) * Kd + kh) : W;

    float4 fa, fw;
    fa = *(const float4*)arow;
    fw = wv ? *(const float4*)wrow : make_float4(0.f,0.f,0.f,0.f);
    {
        float av[4] = {fa.x, fa.y, fa.z, fa.w};
        float wvv[4] = {fw.x, fw.y, fw.z, fw.w};
#pragma unroll
        for (int c = 0; c < 4; c++) { As2[0][kh+c][lr] = pack2(av[c], av[c]); Ws[0][kh+c][lr] = wvv[c]; }
    }
    __syncthreads();

    int ntiles = Kd >> 3;
    for (int tI = 0; tI < ntiles; tI++) {
        int buf = tI & 1;
        bool more = (tI + 1 < ntiles);
        if (more) {
            int k0 = (tI + 1) << 3;
            fa = *(const float4*)(arow + k0);
            if (wv) fw = *(const float4*)(wrow + k0);
        }
#pragma unroll
        for (int k = 0; k < 8; k++) {
            ulonglong2 A01 = *(const ulonglong2*)&As2[buf][k][ty*4];
            ulonglong2 A23 = *(const ulonglong2*)&As2[buf][k][ty*4 + 2];
            ulonglong2 w01 = *(const ulonglong2*)&Ws[buf][k][tx*4];
            ulonglong2 w23 = *(const ulonglong2*)&Ws[buf][k][tx*4 + 32];
            ull am[4] = {A01.x, A01.y, A23.x, A23.y};
#pragma unroll
            for (int i = 0; i < 4; i++) {
                acc[i][0] = fma2(am[i], w01.x, acc[i][0]);
                acc[i][1] = fma2(am[i], w01.y, acc[i][1]);
                acc[i][2] = fma2(am[i], w23.x, acc[i][2]);
                acc[i][3] = fma2(am[i], w23.y, acc[i][3]);
            }
        }
        if (more) {
            int nb = buf ^ 1;
            float av[4] = {fa.x, fa.y, fa.z, fa.w};
            float wvv[4] = {fw.x, fw.y, fw.z, fw.w};
            if (!wv) { wvv[0]=wvv[1]=wvv[2]=wvv[3]=0.f; }
#pragma unroll
            for (int c = 0; c < 4; c++) { As2[nb][kh+c][lr] = pack2(av[c], av[c]); Ws[nb][kh+c][lr] = wvv[c]; }
        }
        __syncthreads();
    }

#pragma unroll
    for (int i = 0; i < 4; i++) {
        int gm = m0 + ty*4 + i;
        float* orow = out + (size_t)gm * N;
        const float* rrow = RES ? (res + (size_t)gm * N) : (const float*)0;
#pragma unroll
        for (int j = 0; j < 4; j++) {
            int gn = n0 + ((j < 2) ? (tx*4 + j*2) : (32 + tx*4 + (j-2)*2));
            float2 v = unpack2(acc[i][j]);
            if (gn < N) {
                float o = v.x;
                if (BIAS) o += bias[gn];
                if (RES)  o += rrow[gn];
                orow[gn] = o;
            }
            if (gn + 1 < N) {
                float o = v.y;
                if (BIAS) o += bias[gn+1];
                if (RES)  o += rrow[gn+1];
                orow[gn+1] = o;
            }
        }
    }
}

// ---------------- causal depthwise conv (K=4) + SiLU ----------------
__global__ void conv_kernel(const float* __restrict__ cw, const float* __restrict__ cb) {
    int i = blockIdx.x * blockDim.x + threadIdx.x;
    if (i >= BL*DIc) return;
    int d  = i % DIc;
    int bl = i / DIc;
    int l  = bl % Ll;
    int b  = bl / Ll;
    float acc = cb[d];
#pragma unroll
    for (int k = 0; k < Kc; ++k) {
        int ls = l - (Kc-1) + k;
        if (ls >= 0)
            acc += cw[d*Kc + k] * g_xz[(size_t)(b*Ll + ls)*(2*DIc) + d];
    }
    float sg = 1.f/(1.f + __expf(-acc));
    g_xact[i] = acc * sg;
}

// ---------------- dt projection (K=24) + softplus + exp/du precompute ----------
__global__ __launch_bounds__(256) void dt_kernel(const float* __restrict__ Wdt,
                                                 const float* __restrict__ bdt) {
    __shared__ float sx[Rr];
    int row = blockIdx.x;
    if (threadIdx.x < Rr) sx[threadIdx.x] = g_xdbl[(size_t)row*XD + threadIdx.x];
    __syncthreads();
    for (int d = threadIdx.x; d < DIc; d += 256) {
        float acc = bdt[d];
#pragma unroll
        for (int r = 0; r < Rr; ++r) acc += sx[r] * Wdt[d*Rr + r];
        float sp = fmaxf(acc, 0.f) + log1pf(__expf(-fabsf(acc)));
        size_t idx = (size_t)row*DIc + d;
        g_dt[idx] = sp;
        g_e[idx]  = __expf(-sp);
        g_du[idx] = sp * g_xact[idx];
    }
}

// ---------------- A precompute + structure check ----------------
__global__ void flag_kernel() { g_powA = 1; }

__global__ void a_kernel(const float* __restrict__ Alog) {
    int i = blockIdx.x*256 + threadIdx.x;
    if (i >= DIc*Sd) return;
    float a = -__expf(Alog[i]);
    g_A[i] = a;
    float tgt = (float)(i % Sd + 1);
    if (fabsf(a + tgt) > 1e-5f * tgt) g_powA = 0;
}

// ---------------- selective scan v4: cp.async shared B/C staging ----------------
struct Chunk { float dt0, dt1, e0, e1, du0, du1, xa0, xa1, z0, z1; };

__device__ __forceinline__ void load_chunk(int b, int tbase, int lane, int ch0, int ch1, Chunk& c) {
    size_t bl = (size_t)b*Ll + tbase + lane;
    size_t i0 = bl*DIc + ch0, i1 = bl*DIc + ch1;
    c.dt0 = g_dt[i0];  c.dt1 = g_dt[i1];
    c.e0  = g_e[i0];   c.e1  = g_e[i1];
    c.du0 = g_du[i0];  c.du1 = g_du[i1];
    c.xa0 = g_xact[i0]; c.xa1 = g_xact[i1];
    c.z0  = g_xz[bl*(2*DIc) + DIc + ch0];
    c.z1  = g_xz[bl*(2*DIc) + DIc + ch1];
}

struct RowU { ull B[4]; ull C[4]; };

__device__ __forceinline__ void cpa16(unsigned dst, const void* src) {
    asm volatile("cp.async.ca.shared.global [%0], [%1], 16;" :: "r"(dst), "l"(src));
}

// one timestep for 2 channels; stores per-lane partials to smem slot
__device__ __forceinline__ void step_update(int ti, int slot, const Chunk& ck, const RowU& r,
                                            ull (&H0)[4], ull (&H1)[4],
                                            bool powA, const float (&a0)[8], const float (&a1)[8],
                                            float nS1, float* yb0, float* yb1, int lane) {
    const unsigned m = 0xffffffffu;
    float dt0 = __shfl_sync(m, ck.dt0, ti);
    float dt1 = __shfl_sync(m, ck.dt1, ti);
    float e0  = __shfl_sync(m, ck.e0,  ti);
    float e1  = __shfl_sync(m, ck.e1,  ti);
    float du0 = __shfl_sync(m, ck.du0, ti);
    float du1 = __shfl_sync(m, ck.du1, ti);
    ull P0[4], P1[4];
    if (powA) {
        float p0 = __expf(dt0 * nS1);   // exp(-dt*(s0+1))
        float p1 = __expf(dt1 * nS1);
        ull E0 = pack2(e0*e0, e0*e0);
        ull E1 = pack2(e1*e1, e1*e1);
        P0[0] = pack2(p0, p0*e0);
        P1[0] = pack2(p1, p1*e1);
        P0[1] = mul2(P0[0], E0); P0[2] = mul2(P0[1], E0); P0[3] = mul2(P0[2], E0);
        P1[1] = mul2(P1[0], E1); P1[2] = mul2(P1[1], E1); P1[3] = mul2(P1[2], E1);
    } else {
#pragma unroll
        for (int j = 0; j < 4; j++) {
            P0[j] = pack2(__expf(dt0*a0[2*j]), __expf(dt0*a0[2*j+1]));
            P1[j] = pack2(__expf(dt1*a1[2*j]), __expf(dt1*a1[2*j+1]));
        }
    }
    ull du0p = pack2(du0, du0);
    ull du1p = pack2(du1, du1);
    ull ya0 = 0ull, ya1 = 0ull;
#pragma unroll
    for (int j = 0; j < 4; j++) {
        H0[j] = fma2(P0[j], H0[j], mul2(du0p, r.B[j]));
        ya0   = fma2(H0[j], r.C[j], ya0);
        H1[j] = fma2(P1[j], H1[j], mul2(du1p, r.B[j]));
        ya1   = fma2(H1[j], r.C[j], ya1);
    }
    float2 u0 = unpack2(ya0);
    float2 u1 = unpack2(ya1);
    yb0[lane*17 + slot] = u0.x + u0.y;
    yb1[lane*17 + slot] = u1.x + u1.y;
}

// grid = Bb * (DIc/8) = 192 blocks, 128 threads (4 warps x 2 channels)
// smem: 3-slot ring (superstep = 4 t, 2KB/t) + per-warp y partial buffers
__global__ __launch_bounds__(128, 1) void scan_kernel(const float* __restrict__ Dvec) {
    __shared__ __align__(16) float ring[3][4*512];   // 24KB
    __shared__ float ybuf[4][2][32*17];              // 17KB
    const int tid  = threadIdx.x;
    const int w    = tid >> 5;
    const int lane = tid & 31;
    const int b    = blockIdx.x / (DIc/8);
    const int dg   = blockIdx.x % (DIc/8);
    const int ch0  = dg*8 + w*2, ch1 = ch0 + 1;
    const int s0   = lane*8;
    const float nS1 = -(float)(s0 + 1);
    const float* xd = g_xdbl + (size_t)b*Ll*XD;
    float* yb0 = ybuf[w][0];
    float* yb1 = ybuf[w][1];

    // per-thread cp.async source mapping: 16B chunk index = tid (covers 512 floats/t)
    const int off = tid * 4;                        // float offset in [0,512)
    const float* srcbase = (off < 256) ? (xd + Rr + off) : (xd + Rr + Sd + (off - 256));
    unsigned ringaddr[3];
#pragma unroll
    for (int s = 0; s < 3; s++)
        ringaddr[s] = (unsigned)__cvta_generic_to_shared(&ring[s][off]);

    ull H0[4] = {}, H1[4] = {};
    float a0[8], a1[8];
    bool powA = (g_powA != 0);
    if (!powA) {
#pragma unroll
        for (int j = 0; j < 8; j++) {
            a0[j] = g_A[(size_t)ch0*Sd + s0 + j];
            a1[j] = g_A[(size_t)ch1*Sd + s0 + j];
        }
    } else {
#pragma unroll
        for (int j = 0; j < 8; j++) { a0[j] = 0.f; a1[j] = 0.f; }
    }
    float D0 = Dvec[ch0], D1 = Dvec[ch1];

    Chunk cur, nxt;
    load_chunk(b, 0, lane, ch0, ch1, cur);
    load_chunk(b, 32, lane, ch0, ch1, nxt);

    // prologue: stage supersteps 0 and 1
#pragma unroll
    for (int ss = 0; ss < 2; ss++) {
        const float* sp = srcbase + (size_t)(ss*4)*XD;
#pragma unroll
        for (int j = 0; j < 4; j++)
            cpa16(ringaddr[ss] + j*2048, sp + (size_t)j*XD);
        asm volatile("cp.async.commit_group;" ::: "memory");
    }

    for (int c = 0; c < Ll/32; c++) {
#pragma unroll
        for (int half = 0; half < 2; half++) {
            for (int q = 0; q < 4; q++) {
                int ss = c*8 + half*4 + q;
                asm volatile("cp.async.wait_group 1;" ::: "memory");
                __syncthreads();
                int slot = ss % 3;
                const float* rb = ring[slot];
#pragma unroll
                for (int j = 0; j < 4; j++) {
                    RowU r;
                    const float* p = rb + j*512;
                    ulonglong2 b01 = *(const ulonglong2*)(p + s0);
                    ulonglong2 b23 = *(const ulonglong2*)(p + s0 + 4);
                    ulonglong2 c01 = *(const ulonglong2*)(p + 256 + s0);
                    ulonglong2 c23 = *(const ulonglong2*)(p + 256 + s0 + 4);
                    r.B[0]=b01.x; r.B[1]=b01.y; r.B[2]=b23.x; r.B[3]=b23.y;
                    r.C[0]=c01.x; r.C[1]=c01.y; r.C[2]=c23.x; r.C[3]=c23.y;
                    int ti = half*16 + q*4 + j;
                    step_update(ti, q*4 + j, cur, r, H0, H1, powA, a0, a1, nS1, yb0, yb1, lane);
                }
                // refill slot (ss+2)%3 for superstep ss+2 (safe: all threads past consume of ss-1)
                int ns = ss + 2;
                if (ns < Ll/4) {
                    const float* sp = srcbase + (size_t)(ns*4)*XD;
#pragma unroll
                    for (int j = 0; j < 4; j++)
                        cpa16(ringaddr[ns % 3] + j*2048, sp + (size_t)j*XD);
                }
                asm volatile("cp.async.commit_group;" ::: "memory");
            }
            __syncwarp();
            // reduce 16 timesteps: lane pairs (l, l+16) share t
            {
                int t15 = lane & 15;
                int lb  = (lane < 16) ? 0 : 16;
                float acc0 = 0.f, acc1 = 0.f;
#pragma unroll
                for (int l = 0; l < 16; l++) {
                    acc0 += yb0[(lb + l)*17 + t15];
                    acc1 += yb1[(lb + l)*17 + t15];
                }
                acc0 += __shfl_xor_sync(0xffffffffu, acc0, 16);
                acc1 += __shfl_xor_sync(0xffffffffu, acc1, 16);
                bool mine = half ? (lane >= 16) : (lane < 16);
                if (mine) {
                    float sg0 = 1.f/(1.f + __expf(-cur.z0));
                    float sg1 = 1.f/(1.f + __expf(-cur.z1));
                    size_t bl = (size_t)b*Ll + c*32 + lane;
                    g_y[bl*DIc + ch0] = (acc0 + D0*cur.xa0) * (cur.z0 * sg0);
                    g_y[bl*DIc + ch1] = (acc1 + D1*cur.xa1) * (cur.z1 * sg1);
                }
            }
            __syncwarp();
        }
        cur = nxt;
        if (c*32 + 64 < Ll) load_chunk(b, c*32 + 64, lane, ch0, ch1, nxt);
    }
}

// ---------------- launcher ----------------
extern "C" void kernel_launch(void* const* d_in, const int* in_sizes, int n_in,
                              void* d_out, int out_size) {
    const float* x          = (const float*)d_in[0];
    const float* ln1_g      = (const float*)d_in[1];
    const float* ln1_b      = (const float*)d_in[2];
    const float* ln2_g      = (const float*)d_in[3];
    const float* ln2_b      = (const float*)d_in[4];
    const float* head_w     = (const float*)d_in[5];
    const float* head_b     = (const float*)d_in[6];
    const float* in_proj_w  = (const float*)d_in[7];
    const float* conv_w     = (const float*)d_in[8];
    const float* conv_b     = (const float*)d_in[9];
    const float* x_proj_w   = (const float*)d_in[10];
    const float* dt_proj_w  = (const float*)d_in[11];
    const float* dt_proj_b  = (const float*)d_in[12];
    const float* A_log      = (const float*)d_in[13];
    const float* Dvec       = (const float*)d_in[14];
    const float* out_proj_w = (const float*)d_in[15];
    float* out = (float*)d_out;

    float *u, *xz, *xact, *xdbl, *yb, *res1, *t2;
    cudaGetSymbolAddress((void**)&u,    g_u);
    cudaGetSymbolAddress((void**)&xz,   g_xz);
    cudaGetSymbolAddress((void**)&xact, g_xact);
    cudaGetSymbolAddress((void**)&xdbl, g_xdbl);
    cudaGetSymbolAddress((void**)&yb,   g_y);
    cudaGetSymbolAddress((void**)&res1, g_res1);
    cudaGetSymbolAddress((void**)&t2,   g_t2);

    // independent precompute for the scan
    flag_kernel<<<1, 1>>>();
    a_kernel<<<(DIc*Sd + 255)/256, 256>>>(A_log);

    // u = ln1(x)
    ln_kernel<<<BL, 128>>>(x, ln1_g, ln1_b, u);

    // xz = u @ in_proj_w^T   (1024 x 1536, K=384)
    gemm_nt<false,false><<<dim3(2*DIc/64, BL/64), 128>>>(u, in_proj_w, nullptr, nullptr,
                                                         xz, BL, 2*DIc, Cc);

    // x_act = silu(conv(x_in) + conv_b)
    conv_kernel<<<(BL*DIc + 255)/256, 256>>>(conv_w, conv_b);

    // x_dbl = x_act @ x_proj_w^T   (1024 x 536, K=768)
    gemm_nt<false,false><<<dim3((XD + 63)/64, BL/64), 128>>>(xact, x_proj_w, nullptr, nullptr,
                                                             xdbl, BL, XD, DIc);

    // dt = softplus(dt_raw @ dt_proj_w^T + dt_proj_b), plus exp(-dt), dt*xact
    dt_kernel<<<BL, 256>>>(dt_proj_w, dt_proj_b);

    // selective scan + D-skip + z-gating -> g_y
    scan_kernel<<<Bb*(DIc/8), 128>>>(Dvec);

    // res1 = g_y @ out_proj_w^T + x   (1024 x 384, K=768)
    gemm_nt<false,true><<<dim3(Cc/64, BL/64), 128>>>(yb, out_proj_w, nullptr, x,
                                                     res1, BL, Cc, DIc);

    // t2 = ln2(res1)
    ln_kernel<<<BL, 128>>>(res1, ln2_g, ln2_b, t2);

    // out = t2 @ head_w^T + head_b + res1
    gemm_nt<true,true><<<dim3(Cc/64, BL/64), 128>>>(t2, head_w, head_b, res1,
                                                    out, BL, Cc, Cc);
}

// round 6
// speedup vs baseline: 1.6519x; 1.2055x over previous
#include <cuda_runtime.h>
#include <math.h>
#include <stdint.h>

#define Cc  384
#define DIc 768
#define Sd  256
#define Rr  24
#define Kc  4
#define Bb  2
#define Ll  512
#define BL  (Bb*Ll)          // 1024
#define XD  (Rr + 2*Sd)      // 536

typedef unsigned long long ull;

// ---------------- f32x2 packed helpers ----------------
__device__ __forceinline__ ull fma2(ull a, ull b, ull c) {
    ull d;
    asm("fma.rn.f32x2 %0, %1, %2, %3;" : "=l"(d) : "l"(a), "l"(b), "l"(c));
    return d;
}
__device__ __forceinline__ ull mul2(ull a, ull b) {
    ull d;
    asm("mul.rn.f32x2 %0, %1, %2;" : "=l"(d) : "l"(a), "l"(b));
    return d;
}
__device__ __forceinline__ ull pack2(float x, float y) {
    ull d;
    asm("mov.b64 %0, {%1, %2};" : "=l"(d) : "f"(x), "f"(y));
    return d;
}
__device__ __forceinline__ float2 unpack2(ull v) {
    float2 r;
    asm("mov.b64 {%0, %1}, %2;" : "=f"(r.x), "=f"(r.y) : "l"(v));
    return r;
}

__device__ __forceinline__ void cpa16(uint32_t dst, const void* src) {
    asm volatile("cp.async.ca.shared.global [%0], [%1], 16;" :: "r"(dst), "l"(src));
}
__device__ __forceinline__ uint32_t f2tf(float f) {
    uint32_t r;
    asm("cvt.rna.tf32.f32 %0, %1;" : "=r"(r) : "f"(f));
    return r;
}
__device__ __forceinline__ void mma8(float* c, const uint32_t* a, const uint32_t* b) {
    asm volatile(
        "mma.sync.aligned.m16n8k8.row.col.f32.tf32.tf32.f32 "
        "{%0,%1,%2,%3}, {%4,%5,%6,%7}, {%8,%9}, {%0,%1,%2,%3};"
        : "+f"(c[0]), "+f"(c[1]), "+f"(c[2]), "+f"(c[3])
        : "r"(a[0]), "r"(a[1]), "r"(a[2]), "r"(a[3]), "r"(b[0]), "r"(b[1]));
}

// ---------------- scratch ----------------
__device__ __align__(16) float g_u[BL*Cc];
__device__ __align__(16) float g_xz[BL*2*DIc];
__device__ __align__(16) float g_xact[BL*DIc];
__device__ __align__(16) float g_xdbl[BL*XD];
__device__ __align__(16) float g_dt[BL*DIc];
__device__ __align__(16) float g_e[BL*DIc];
__device__ __align__(16) float g_du[BL*DIc];
__device__ __align__(16) float g_A[DIc*Sd];
__device__ int   g_powA;
__device__ __align__(16) float g_y[BL*DIc];
__device__ __align__(16) float g_res1[BL*Cc];
__device__ __align__(16) float g_t2[BL*Cc];

// ---------------- LayerNorm ----------------
__global__ __launch_bounds__(128) void ln_kernel(const float* __restrict__ x,
                                                 const float* __restrict__ gw,
                                                 const float* __restrict__ bw,
                                                 float* __restrict__ out) {
    int row = blockIdx.x;
    const float* xr = x + (size_t)row * Cc;
    float v[3];
#pragma unroll
    for (int i = 0; i < 3; i++) v[i] = xr[threadIdx.x + i*128];
    float s = v[0]+v[1]+v[2];
    float q = v[0]*v[0]+v[1]*v[1]+v[2]*v[2];
#pragma unroll
    for (int o = 16; o; o >>= 1) {
        s += __shfl_xor_sync(0xffffffffu, s, o);
        q += __shfl_xor_sync(0xffffffffu, q, o);
    }
    __shared__ float sh[8];
    int wid = threadIdx.x >> 5, ln = threadIdx.x & 31;
    if (ln == 0) { sh[wid] = s; sh[wid+4] = q; }
    __syncthreads();
    s = sh[0]+sh[1]+sh[2]+sh[3];
    q = sh[4]+sh[5]+sh[6]+sh[7];
    float mu  = s * (1.f/Cc);
    float var = q * (1.f/Cc) - mu*mu;
    float rs  = rsqrtf(var + 1e-5f);
#pragma unroll
    for (int i = 0; i < 3; i++) {
        int c = threadIdx.x + i*128;
        out[(size_t)row*Cc + c] = (v[i]-mu)*rs*gw[c] + bw[c];
    }
}

// ------------- tf32 mma.sync GEMM: out[M,N]=A[M,K]·W[N,K]^T (+bias)(+res) -------
// block 256 thr (8 warps), tile 128(M)x64(N), warp tile 32x32, K-chunk 32.
// THREE: 3xTF32 (hi/lo split) for fp32-class accuracy.
// Layout in smem: rows x 36-float pitch (conflict-free for mma lane mapping).
#define GP 36
#define ABUF (128*GP)
#define WBUF (64*GP)
#define TGF (2*(ABUF+WBUF))          // floats
#define TG_SMEM (TGF*4)              // 55296 bytes

__device__ __forceinline__ void tg_stage(const float* __restrict__ A,
                                         const float* __restrict__ W,
                                         int N, int Kd, int m0, int n0, int i,
                                         uint32_t Au, uint32_t Wu, int tid) {
    int k0 = i << 5;
#pragma unroll
    for (int j = 0; j < 4; j++) {
        int idx = tid + j*256;
        int r = idx >> 3, c = idx & 7;
        cpa16(Au + (unsigned)(r*GP + c*4)*4, A + (size_t)(m0+r)*Kd + k0 + c*4);
    }
#pragma unroll
    for (int j = 0; j < 2; j++) {
        int idx = tid + j*256;
        int r = idx >> 3, c = idx & 7;
        uint32_t dst = Wu + (unsigned)(r*GP + c*4)*4;
        int gn = n0 + r;
        if (gn < N)
            cpa16(dst, W + (size_t)gn*Kd + k0 + c*4);
        else
            asm volatile("st.shared.v4.b32 [%0], {%1,%1,%1,%1};" :: "r"(dst), "r"(0u) : "memory");
    }
    asm volatile("cp.async.commit_group;" ::: "memory");
}

template<bool BIAS, bool RES, bool THREE>
__global__ __launch_bounds__(256) void tgemm(const float* __restrict__ A,
                                             const float* __restrict__ W,
                                             const float* __restrict__ bias,
                                             const float* __restrict__ res,
                                             float* __restrict__ out,
                                             int M, int N, int Kd) {
    extern __shared__ float sm[];
    uint32_t sb;
    asm("{ .reg .u64 t; cvta.to.shared.u64 t, %1; cvt.u32.u64 %0, t; }" : "=r"(sb) : "l"(sm));
    const int tid = threadIdx.x, lane = tid & 31, wid = tid >> 5;
    const int wm = wid & 3, wn = wid >> 2;
    const int m0 = blockIdx.y * 128, n0 = blockIdx.x * 64;
    const int nch = Kd >> 5;

    float* Ab[2] = { sm,             sm + ABUF + WBUF };
    float* Wb[2] = { sm + ABUF,      sm + 2*ABUF + WBUF };
    uint32_t Au[2] = { sb,                    sb + (ABUF + WBUF)*4 };
    uint32_t Wu[2] = { sb + ABUF*4,           sb + (2*ABUF + WBUF)*4 };

    float acc[2][4][4] = {};

    tg_stage(A, W, N, Kd, m0, n0, 0, Au[0], Wu[0], tid);
    if (nch > 1) tg_stage(A, W, N, Kd, m0, n0, 1, Au[1], Wu[1], tid);

    const int lq = lane >> 2, lr = lane & 3;

    for (int i = 0; i < nch; i++) {
        int buf = i & 1;
        if (i + 1 < nch) asm volatile("cp.async.wait_group 1;" ::: "memory");
        else             asm volatile("cp.async.wait_group 0;" ::: "memory");
        __syncthreads();
        const float* Ap = Ab[buf];
        const float* Wp = Wb[buf];
#pragma unroll
        for (int k8 = 0; k8 < 4; k8++) {
            int kb = k8*8 + lr;
            // A fragments (2 m-tiles), hi and optional lo
            uint32_t ah[2][4], al[2][4];
#pragma unroll
            for (int t = 0; t < 2; t++) {
                int rb = wm*32 + t*16 + lq;
                float v0 = Ap[rb*GP + kb];
                float v1 = Ap[(rb+8)*GP + kb];
                float v2 = Ap[rb*GP + kb + 4];
                float v3 = Ap[(rb+8)*GP + kb + 4];
                ah[t][0] = f2tf(v0); ah[t][1] = f2tf(v1);
                ah[t][2] = f2tf(v2); ah[t][3] = f2tf(v3);
                if (THREE) {
                    al[t][0] = f2tf(v0 - __uint_as_float(ah[t][0]));
                    al[t][1] = f2tf(v1 - __uint_as_float(ah[t][1]));
                    al[t][2] = f2tf(v2 - __uint_as_float(ah[t][2]));
                    al[t][3] = f2tf(v3 - __uint_as_float(ah[t][3]));
                }
            }
            uint32_t bh[4][2], blo[4][2];
#pragma unroll
            for (int j = 0; j < 4; j++) {
                int nb = wn*32 + j*8 + lq;
                float v0 = Wp[nb*GP + kb];
                float v1 = Wp[nb*GP + kb + 4];
                bh[j][0] = f2tf(v0); bh[j][1] = f2tf(v1);
                if (THREE) {
                    blo[j][0] = f2tf(v0 - __uint_as_float(bh[j][0]));
                    blo[j][1] = f2tf(v1 - __uint_as_float(bh[j][1]));
                }
            }
#pragma unroll
            for (int t = 0; t < 2; t++)
#pragma unroll
                for (int j = 0; j < 4; j++) {
                    mma8(acc[t][j], ah[t], bh[j]);
                    if (THREE) {
                        mma8(acc[t][j], ah[t], blo[j]);
                        mma8(acc[t][j], al[t], bh[j]);
                    }
                }
        }
        if (i + 2 < nch) {
            __syncthreads();
            tg_stage(A, W, N, Kd, m0, n0, i + 2, Au[buf], Wu[buf], tid);
        }
    }

#pragma unroll
    for (int t = 0; t < 2; t++) {
        int r0 = m0 + wm*32 + t*16 + lq;
#pragma unroll
        for (int j = 0; j < 4; j++) {
            int gn = n0 + wn*32 + j*8 + lr*2;
            if (gn >= N) continue;
            const float* c = acc[t][j];
            float o0 = c[0], o1 = c[1], o2 = c[2], o3 = c[3];
            if (BIAS) { float b0 = bias[gn], b1 = bias[gn+1]; o0 += b0; o1 += b1; o2 += b0; o3 += b1; }
            float* p0 = out + (size_t)r0 * N + gn;
            float* p1 = out + (size_t)(r0+8) * N + gn;
            if (RES) {
                const float* q0 = res + (size_t)r0 * N + gn;
                const float* q1 = res + (size_t)(r0+8) * N + gn;
                o0 += q0[0]; o1 += q0[1]; o2 += q1[0]; o3 += q1[1];
            }
            p0[0] = o0; p0[1] = o1;
            p1[0] = o2; p1[1] = o3;
        }
    }
}

// ---------------- causal depthwise conv (K=4) + SiLU ----------------
__global__ void conv_kernel(const float* __restrict__ cw, const float* __restrict__ cb) {
    int i = blockIdx.x * blockDim.x + threadIdx.x;
    if (i >= BL*DIc) return;
    int d  = i % DIc;
    int bl = i / DIc;
    int l  = bl % Ll;
    int b  = bl / Ll;
    float acc = cb[d];
#pragma unroll
    for (int k = 0; k < Kc; ++k) {
        int ls = l - (Kc-1) + k;
        if (ls >= 0)
            acc += cw[d*Kc + k] * g_xz[(size_t)(b*Ll + ls)*(2*DIc) + d];
    }
    float sg = 1.f/(1.f + __expf(-acc));
    g_xact[i] = acc * sg;
}

// ---------- dt: exact fp32 x_proj dt-slice + dt_proj + softplus + exp/du --------
__global__ __launch_bounds__(192) void dt_kernel(const float* __restrict__ Wx,
                                                 const float* __restrict__ Wdt,
                                                 const float* __restrict__ bdt) {
    __shared__ float sx[DIc];
    __shared__ float sdt[Rr];
    int row = blockIdx.x, tid = threadIdx.x;
    const float* xr = g_xact + (size_t)row * DIc;
    for (int i = tid; i < DIc; i += 192) sx[i] = xr[i];
    __syncthreads();
    int r = tid >> 3, sl = tid & 7;
    const float* wrow = Wx + (size_t)r * DIc;
    float acc = 0.f;
    for (int k = sl; k < DIc; k += 8) acc += sx[k] * wrow[k];
    acc += __shfl_xor_sync(0xffffffffu, acc, 4);
    acc += __shfl_xor_sync(0xffffffffu, acc, 2);
    acc += __shfl_xor_sync(0xffffffffu, acc, 1);
    if (sl == 0) sdt[r] = acc;
    __syncthreads();
    for (int d = tid; d < DIc; d += 192) {
        float a = bdt[d];
#pragma unroll
        for (int rr = 0; rr < Rr; rr++) a += sdt[rr] * Wdt[d*Rr + rr];
        float sp = fmaxf(a, 0.f) + log1pf(__expf(-fabsf(a)));
        size_t idx = (size_t)row*DIc + d;
        g_dt[idx] = sp;
        g_e[idx]  = __expf(-sp);
        g_du[idx] = sp * sx[d];
    }
}

// ---------------- A precompute + structure check ----------------
__global__ void flag_kernel() { g_powA = 1; }

__global__ void a_kernel(const float* __restrict__ Alog) {
    int i = blockIdx.x*256 + threadIdx.x;
    if (i >= DIc*Sd) return;
    float a = -__expf(Alog[i]);
    g_A[i] = a;
    float tgt = (float)(i % Sd + 1);
    if (fabsf(a + tgt) > 1e-5f * tgt) g_powA = 0;
}

// ---------------- selective scan (cp.async shared B/C staging) ------------------
struct Chunk { float dt0, dt1, e0, e1, du0, du1, xa0, xa1, z0, z1; };

__device__ __forceinline__ void load_chunk(int b, int tbase, int lane, int ch0, int ch1, Chunk& c) {
    size_t bl = (size_t)b*Ll + tbase + lane;
    size_t i0 = bl*DIc + ch0, i1 = bl*DIc + ch1;
    c.dt0 = g_dt[i0];  c.dt1 = g_dt[i1];
    c.e0  = g_e[i0];   c.e1  = g_e[i1];
    c.du0 = g_du[i0];  c.du1 = g_du[i1];
    c.xa0 = g_xact[i0]; c.xa1 = g_xact[i1];
    c.z0  = g_xz[bl*(2*DIc) + DIc + ch0];
    c.z1  = g_xz[bl*(2*DIc) + DIc + ch1];
}

struct RowU { ull B[4]; ull C[4]; };

__device__ __forceinline__ void step_update(int ti, int slot, const Chunk& ck, const RowU& r,
                                            ull (&H0)[4], ull (&H1)[4],
                                            bool powA, const float (&a0)[8], const float (&a1)[8],
                                            float nS1, float* yb0, float* yb1, int lane) {
    const unsigned m = 0xffffffffu;
    float dt0 = __shfl_sync(m, ck.dt0, ti);
    float dt1 = __shfl_sync(m, ck.dt1, ti);
    float e0  = __shfl_sync(m, ck.e0,  ti);
    float e1  = __shfl_sync(m, ck.e1,  ti);
    float du0 = __shfl_sync(m, ck.du0, ti);
    float du1 = __shfl_sync(m, ck.du1, ti);
    ull P0[4], P1[4];
    if (powA) {
        float p0 = __expf(dt0 * nS1);
        float p1 = __expf(dt1 * nS1);
        ull E0 = pack2(e0*e0, e0*e0);
        ull E1 = pack2(e1*e1, e1*e1);
        P0[0] = pack2(p0, p0*e0);
        P1[0] = pack2(p1, p1*e1);
        P0[1] = mul2(P0[0], E0); P0[2] = mul2(P0[1], E0); P0[3] = mul2(P0[2], E0);
        P1[1] = mul2(P1[0], E1); P1[2] = mul2(P1[1], E1); P1[3] = mul2(P1[2], E1);
    } else {
#pragma unroll
        for (int j = 0; j < 4; j++) {
            P0[j] = pack2(__expf(dt0*a0[2*j]), __expf(dt0*a0[2*j+1]));
            P1[j] = pack2(__expf(dt1*a1[2*j]), __expf(dt1*a1[2*j+1]));
        }
    }
    ull du0p = pack2(du0, du0);
    ull du1p = pack2(du1, du1);
    ull ya0 = 0ull, ya1 = 0ull;
#pragma unroll
    for (int j = 0; j < 4; j++) {
        H0[j] = fma2(P0[j], H0[j], mul2(du0p, r.B[j]));
        ya0   = fma2(H0[j], r.C[j], ya0);
        H1[j] = fma2(P1[j], H1[j], mul2(du1p, r.B[j]));
        ya1   = fma2(H1[j], r.C[j], ya1);
    }
    float2 u0 = unpack2(ya0);
    float2 u1 = unpack2(ya1);
    yb0[lane*17 + slot] = u0.x + u0.y;
    yb1[lane*17 + slot] = u1.x + u1.y;
}

__global__ __launch_bounds__(128, 1) void scan_kernel(const float* __restrict__ Dvec) {
    __shared__ __align__(16) float ring[3][4*512];
    __shared__ float ybuf[4][2][32*17];
    const int tid  = threadIdx.x;
    const int w    = tid >> 5;
    const int lane = tid & 31;
    const int b    = blockIdx.x / (DIc/8);
    const int dg   = blockIdx.x % (DIc/8);
    const int ch0  = dg*8 + w*2, ch1 = ch0 + 1;
    const int s0   = lane*8;
    const float nS1 = -(float)(s0 + 1);
    const float* xd = g_xdbl + (size_t)b*Ll*XD;
    float* yb0 = ybuf[w][0];
    float* yb1 = ybuf[w][1];

    const int off = tid * 4;
    const float* srcbase = (off < 256) ? (xd + Rr + off) : (xd + Rr + Sd + (off - 256));
    unsigned ringaddr[3];
#pragma unroll
    for (int s = 0; s < 3; s++)
        ringaddr[s] = (unsigned)__cvta_generic_to_shared(&ring[s][off]);

    ull H0[4] = {}, H1[4] = {};
    float a0[8], a1[8];
    bool powA = (g_powA != 0);
    if (!powA) {
#pragma unroll
        for (int j = 0; j < 8; j++) {
            a0[j] = g_A[(size_t)ch0*Sd + s0 + j];
            a1[j] = g_A[(size_t)ch1*Sd + s0 + j];
        }
    } else {
#pragma unroll
        for (int j = 0; j < 8; j++) { a0[j] = 0.f; a1[j] = 0.f; }
    }
    float D0 = Dvec[ch0], D1 = Dvec[ch1];

    Chunk cur, nxt;
    load_chunk(b, 0, lane, ch0, ch1, cur);
    load_chunk(b, 32, lane, ch0, ch1, nxt);

#pragma unroll
    for (int ss = 0; ss < 2; ss++) {
        const float* sp = srcbase + (size_t)(ss*4)*XD;
#pragma unroll
        for (int j = 0; j < 4; j++)
            cpa16(ringaddr[ss] + j*2048, sp + (size_t)j*XD);
        asm volatile("cp.async.commit_group;" ::: "memory");
    }

    for (int c = 0; c < Ll/32; c++) {
#pragma unroll
        for (int half = 0; half < 2; half++) {
            for (int q = 0; q < 4; q++) {
                int ss = c*8 + half*4 + q;
                asm volatile("cp.async.wait_group 1;" ::: "memory");
                __syncthreads();
                int slot = ss % 3;
                const float* rb = ring[slot];
#pragma unroll
                for (int j = 0; j < 4; j++) {
                    RowU r;
                    const float* p = rb + j*512;
                    ulonglong2 b01 = *(const ulonglong2*)(p + s0);
                    ulonglong2 b23 = *(const ulonglong2*)(p + s0 + 4);
                    ulonglong2 c01 = *(const ulonglong2*)(p + 256 + s0);
                    ulonglong2 c23 = *(const ulonglong2*)(p + 256 + s0 + 4);
                    r.B[0]=b01.x; r.B[1]=b01.y; r.B[2]=b23.x; r.B[3]=b23.y;
                    r.C[0]=c01.x; r.C[1]=c01.y; r.C[2]=c23.x; r.C[3]=c23.y;
                    int ti = half*16 + q*4 + j;
                    step_update(ti, q*4 + j, cur, r, H0, H1, powA, a0, a1, nS1, yb0, yb1, lane);
                }
                int ns = ss + 2;
                if (ns < Ll/4) {
                    const float* sp = srcbase + (size_t)(ns*4)*XD;
#pragma unroll
                    for (int j = 0; j < 4; j++)
                        cpa16(ringaddr[ns % 3] + j*2048, sp + (size_t)j*XD);
                }
                asm volatile("cp.async.commit_group;" ::: "memory");
            }
            __syncwarp();
            {
                int t15 = lane & 15;
                int lb  = (lane < 16) ? 0 : 16;
                float acc0 = 0.f, acc1 = 0.f;
#pragma unroll
                for (int l = 0; l < 16; l++) {
                    acc0 += yb0[(lb + l)*17 + t15];
                    acc1 += yb1[(lb + l)*17 + t15];
                }
                acc0 += __shfl_xor_sync(0xffffffffu, acc0, 16);
                acc1 += __shfl_xor_sync(0xffffffffu, acc1, 16);
                bool mine = half ? (lane >= 16) : (lane < 16);
                if (mine) {
                    float sg0 = 1.f/(1.f + __expf(-cur.z0));
                    float sg1 = 1.f/(1.f + __expf(-cur.z1));
                    size_t bl = (size_t)b*Ll + c*32 + lane;
                    g_y[bl*DIc + ch0] = (acc0 + D0*cur.xa0) * (cur.z0 * sg0);
                    g_y[bl*DIc + ch1] = (acc1 + D1*cur.xa1) * (cur.z1 * sg1);
                }
            }
            __syncwarp();
        }
        cur = nxt;
        if (c*32 + 64 < Ll) load_chunk(b, c*32 + 64, lane, ch0, ch1, nxt);
    }
}

// ---------------- launcher ----------------
extern "C" void kernel_launch(void* const* d_in, const int* in_sizes, int n_in,
                              void* d_out, int out_size) {
    const float* x          = (const float*)d_in[0];
    const float* ln1_g      = (const float*)d_in[1];
    const float* ln1_b      = (const float*)d_in[2];
    const float* ln2_g      = (const float*)d_in[3];
    const float* ln2_b      = (const float*)d_in[4];
    const float* head_w     = (const float*)d_in[5];
    const float* head_b     = (const float*)d_in[6];
    const float* in_proj_w  = (const float*)d_in[7];
    const float* conv_w     = (const float*)d_in[8];
    const float* conv_b     = (const float*)d_in[9];
    const float* x_proj_w   = (const float*)d_in[10];
    const float* dt_proj_w  = (const float*)d_in[11];
    const float* dt_proj_b  = (const float*)d_in[12];
    const float* A_log      = (const float*)d_in[13];
    const float* Dvec       = (const float*)d_in[14];
    const float* out_proj_w = (const float*)d_in[15];
    float* out = (float*)d_out;

    float *u, *xz, *xact, *xdbl, *yb, *res1, *t2;
    cudaGetSymbolAddress((void**)&u,    g_u);
    cudaGetSymbolAddress((void**)&xz,   g_xz);
    cudaGetSymbolAddress((void**)&xact, g_xact);
    cudaGetSymbolAddress((void**)&xdbl, g_xdbl);
    cudaGetSymbolAddress((void**)&yb,   g_y);
    cudaGetSymbolAddress((void**)&res1, g_res1);
    cudaGetSymbolAddress((void**)&t2,   g_t2);

    cudaFuncSetAttribute(tgemm<false,false,true>,  cudaFuncAttributeMaxDynamicSharedMemorySize, TG_SMEM);
    cudaFuncSetAttribute(tgemm<false,false,false>, cudaFuncAttributeMaxDynamicSharedMemorySize, TG_SMEM);
    cudaFuncSetAttribute(tgemm<false,true,false>,  cudaFuncAttributeMaxDynamicSharedMemorySize, TG_SMEM);
    cudaFuncSetAttribute(tgemm<true,true,false>,   cudaFuncAttributeMaxDynamicSharedMemorySize, TG_SMEM);

    flag_kernel<<<1, 1>>>();
    a_kernel<<<(DIc*Sd + 255)/256, 256>>>(A_log);

    // u = ln1(x)
    ln_kernel<<<BL, 128>>>(x, ln1_g, ln1_b, u);

    // xz = u @ in_proj_w^T  (1024 x 1536, K=384)  — 3xTF32 (feeds dt/exp path)
    tgemm<false,false,true><<<dim3(2*DIc/64, BL/128), 256, TG_SMEM>>>(u, in_proj_w, nullptr, nullptr,
                                                                      xz, BL, 2*DIc, Cc);

    // x_act = silu(conv(x_in) + conv_b)
    conv_kernel<<<(BL*DIc + 255)/256, 256>>>(conv_w, conv_b);

    // x_dbl = x_act @ x_proj_w^T  (1024 x 536, K=768) — tf32 (B/C linear paths)
    tgemm<false,false,false><<<dim3((XD + 63)/64, BL/128), 256, TG_SMEM>>>(xact, x_proj_w, nullptr, nullptr,
                                                                           xdbl, BL, XD, DIc);

    // dt = softplus(exact fp32 dt-slice @ dt_proj_w^T + b), exp(-dt), dt*xact
    dt_kernel<<<BL, 192>>>(x_proj_w, dt_proj_w, dt_proj_b);

    // selective scan + D-skip + z-gating -> g_y
    scan_kernel<<<Bb*(DIc/8), 128>>>(Dvec);

    // res1 = g_y @ out_proj_w^T + x  (1024 x 384, K=768) — tf32
    tgemm<false,true,false><<<dim3(Cc/64, BL/128), 256, TG_SMEM>>>(yb, out_proj_w, nullptr, x,
                                                                   res1, BL, Cc, DIc);

    // t2 = ln2(res1)
    ln_kernel<<<BL, 128>>>(res1, ln2_g, ln2_b, t2);

    // out = t2 @ head_w^T + head_b + res1 — tf32
    tgemm<true,true,false><<<dim3(Cc/64, BL/128), 256, TG_SMEM>>>(t2, head_w, head_b, res1,
                                                                  out, BL, Cc, Cc);
}